// round 3
// baseline (speedup 1.0000x reference)
#include <cuda_runtime.h>
#include <math.h>

#define D      512
#define LR     64
#define E      4
#define EL     256      // E * LR
#define CROSS  3
#define ROWS   64       // rows per CTA
#define THREADS 512
#define KB     16       // k-block per stage

typedef unsigned long long u64;

// Scratch for transposed U weights: w2t[i][d][el] = Us[i][e][d][l], el = e*64+l
__device__ float g_w2t[CROSS * D * EL];
// Transposed gate: gwt[e][d] = gate_w[d][e]
__device__ float g_gwt[E * D];

__global__ void prep_kernel(const float* __restrict__ Us,
                            const float* __restrict__ gate_w) {
    int idx = blockIdx.x * blockDim.x + threadIdx.x;
    const int NW = CROSS * D * EL;
    if (idx < NW) {
        int i   = idx / (D * EL);
        int rem = idx % (D * EL);
        int d   = rem / EL;
        int el  = rem % EL;
        int e   = el / LR;
        int l   = el % LR;
        g_w2t[idx] = Us[((i * E + e) * D + d) * LR + l];
    } else if (idx < NW + E * D) {
        int j = idx - NW;
        int e = j / D, d = j % D;
        g_gwt[j] = gate_w[d * E + e];
    }
}

__device__ __forceinline__ float4 ld4(const float* p) {
    return *reinterpret_cast<const float4*>(p);
}
__device__ __forceinline__ ulonglong2 ld2u64(const float* p) {
    return *reinterpret_cast<const ulonglong2*>(p);
}
__device__ __forceinline__ void ffma2(u64& acc, u64 a, u64 b) {
    asm("fma.rn.f32x2 %0, %1, %2, %0;" : "+l"(acc) : "l"(a), "l"(b));
}
__device__ __forceinline__ u64 pack2(float x) {
    u64 r;
    asm("mov.b64 %0, {%1, %1};" : "=l"(r) : "f"(x));
    return r;
}
__device__ __forceinline__ float2 unpack2(u64 v) {
    float2 r;
    asm("mov.b64 {%0, %1}, %2;" : "=f"(r.x), "=f"(r.y) : "l"(v));
    return r;
}
__device__ __forceinline__ float fast_tanh(float x) {
    asm("tanh.approx.f32 %0, %0;" : "+f"(x));
    return x;
}

// Shared-memory GEMM with packed f32x2 FMA.
// 16 warps: warp w covers rows (w&7)*8..+8 and cols (w>>3)*128..+128.
// Lane covers 4 cols (2 packed pairs) x 8 rows -> acc2[8][2].
// Weights staged KB=16 deep in sW[KB][EL], written by all 512 threads.
// BD = block-diagonal C-phase: X k-offset depends on the e-block of the columns.
template<int KTOT, int XS, bool BD>
__device__ __forceinline__ void gemm_acc(
    const float* __restrict__ Wg, int ws,
    const float* __restrict__ sX, float* __restrict__ sW,
    u64 acc2[8][2], int tid)
{
    const int warp = tid >> 5, lane = tid & 31;
    const int r0 = (warp & 7) * 8;
    const int cA = (warp >> 3) * 128 + lane * 4;
    const int oA = BD ? ((cA >> 6) * LR) : 0;

    // weight staging: thread t handles col = t & 255, k-half = (t >> 8) * 8
    const int wcol = tid & 255;
    const int kh   = (tid >> 8) * 8;
    const float* gp = Wg + wcol * ws + kh;

    // prefetch first weight block
    float4 wa = ld4(gp + 0);
    float4 wb = ld4(gp + 4);

    #pragma unroll 1
    for (int kb = 0; kb < KTOT / KB; ++kb) {
        __syncthreads();                       // prior consumers of sW done
        sW[(kh+0)*EL + wcol] = wa.x; sW[(kh+1)*EL + wcol] = wa.y;
        sW[(kh+2)*EL + wcol] = wa.z; sW[(kh+3)*EL + wcol] = wa.w;
        sW[(kh+4)*EL + wcol] = wb.x; sW[(kh+5)*EL + wcol] = wb.y;
        sW[(kh+6)*EL + wcol] = wb.z; sW[(kh+7)*EL + wcol] = wb.w;
        if (kb + 1 < KTOT / KB) {              // overlap next global read w/ compute
            wa = ld4(gp + (kb + 1) * KB);
            wb = ld4(gp + (kb + 1) * KB + 4);
        }
        __syncthreads();

        #pragma unroll
        for (int h = 0; h < 4; ++h) {
            float4 xA[8];
            #pragma unroll
            for (int i = 0; i < 8; ++i)
                xA[i] = ld4(sX + (r0 + i) * XS + oA + kb * KB + h * 4);
            #pragma unroll
            for (int kk = 0; kk < 4; ++kk) {
                ulonglong2 wA = ld2u64(sW + (h * 4 + kk) * EL + cA);
                #pragma unroll
                for (int i = 0; i < 8; ++i) {
                    u64 xp = pack2((&xA[i].x)[kk]);
                    ffma2(acc2[i][0], xp, wA.x);
                    ffma2(acc2[i][1], xp, wA.y);
                }
            }
        }
    }
}

#define ZERO_ACC(acc2)                        \
    _Pragma("unroll")                         \
    for (int zi = 0; zi < 8; ++zi)            \
        _Pragma("unroll")                     \
        for (int zj = 0; zj < 2; ++zj)        \
            acc2[zi][zj] = 0ull;

// smem floats: sXL 64*512, sACT 64*256, sW 16*256, sG 64*4, sGS 64
#define SMEM_FLOATS (ROWS * D + ROWS * EL + KB * EL + ROWS * E + ROWS)
#define SMEM_BYTES  (SMEM_FLOATS * 4)

__global__ void __launch_bounds__(THREADS, 1)
dcn_kernel(const float* __restrict__ x,
           const float* __restrict__ Vs,
           const float* __restrict__ Cs,
           const float* __restrict__ bias,
           float* __restrict__ out)
{
    extern __shared__ float smem[];
    float* sXL  = smem;                    // [ROWS][D]
    float* sACT = sXL  + ROWS * D;         // [ROWS][EL]
    float* sW   = sACT + ROWS * EL;        // [KB][EL]
    float* sG   = sW   + KB * EL;          // [ROWS][E]
    float* sGS  = sG   + ROWS * E;         // [ROWS]

    const int tid  = threadIdx.x;
    const int bid  = blockIdx.x;
    const int row0 = bid * ROWS;
    const int warp = tid >> 5, lane = tid & 31;
    const int r0 = (warp & 7) * 8;
    const int cA = (warp >> 3) * 128 + lane * 4;

    // Load x tile into sXL
    {
        const float4* src = reinterpret_cast<const float4*>(x + (size_t)row0 * D);
        float4* dst = reinterpret_cast<float4*>(sXL);
        for (int i = tid; i < ROWS * D / 4; i += THREADS) dst[i] = src[i];
    }

    u64 acc2[8][2];

    for (int layer = 0; layer < CROSS; ++layer) {
        __syncthreads();   // sXL (prev layer epilogue / initial load) visible

        // ---- gate: g[r][e] = dot(x_l[r], gate_w[:,e]) ----
        if (tid < ROWS * E) {
            int r = tid >> 2, e = tid & 3;
            const float* xr = sXL + r * D;
            const float* gw = g_gwt + e * D;
            float g = 0.f;
            #pragma unroll 8
            for (int k = 0; k < D; k += 4) {
                float4 xv = ld4(xr + k);
                float4 wv = ld4(gw + k);
                g += xv.x * wv.x + xv.y * wv.y + xv.z * wv.z + xv.w * wv.w;
            }
            sG[tid] = g;
        }
        __syncthreads();
        if (tid < ROWS)
            sGS[tid] = sG[tid * 4] + sG[tid * 4 + 1] + sG[tid * 4 + 2] + sG[tid * 4 + 3];
        // (ordered by the sync inside the first gemm_acc iteration)

        // ---- V phase: v = tanh(Vs[i] @ x_l)  [64 x 256] ----
        ZERO_ACC(acc2);
        gemm_acc<D, D, false>(Vs + (size_t)layer * EL * D, D, sXL, sW, acc2, tid);
        #pragma unroll
        for (int i = 0; i < 8; ++i) {
            float2 p0 = unpack2(acc2[i][0]), p1 = unpack2(acc2[i][1]);
            float4 va = make_float4(fast_tanh(p0.x), fast_tanh(p0.y),
                                    fast_tanh(p1.x), fast_tanh(p1.y));
            *reinterpret_cast<float4*>(sACT + (r0 + i) * EL + cA) = va;
        }

        // ---- C phase (block diagonal): c' = g_e * tanh(Cs[i,e] @ v_e) ----
        ZERO_ACC(acc2);
        gemm_acc<LR, EL, true>(Cs + (size_t)layer * EL * LR, LR, sACT, sW, acc2, tid);
        __syncthreads();   // all reads of v complete before overwrite
        {
            const int eA = cA >> 6;
            #pragma unroll
            for (int i = 0; i < 8; ++i) {
                float ga = sG[(r0 + i) * 4 + eA];
                float2 p0 = unpack2(acc2[i][0]), p1 = unpack2(acc2[i][1]);
                float4 ca = make_float4(ga * fast_tanh(p0.x), ga * fast_tanh(p0.y),
                                        ga * fast_tanh(p1.x), ga * fast_tanh(p1.y));
                *reinterpret_cast<float4*>(sACT + (r0 + i) * EL + cA) = ca;
            }
        }

        // ---- U phase (two 256-col halves): x_l += x0*(U@c' + bias*sum_g) ----
        for (int half = 0; half < 2; ++half) {
            ZERO_ACC(acc2);
            gemm_acc<EL, EL, false>(
                g_w2t + (size_t)layer * D * EL + (size_t)half * 256 * EL,
                EL, sACT, sW, acc2, tid);
            #pragma unroll
            for (int i = 0; i < 8; ++i) {
                int r  = r0 + i;
                float gs = sGS[r];
                int dA = half * 256 + cA;
                float2 p0 = unpack2(acc2[i][0]), p1 = unpack2(acc2[i][1]);
                float4 bA  = ld4(bias + layer * D + dA);
                float4 x0A = ld4(x + (size_t)(row0 + r) * D + dA);
                float4 xlA = ld4(sXL + r * D + dA);
                float4 oA;
                oA.x = x0A.x * (p0.x + bA.x * gs) + xlA.x;
                oA.y = x0A.y * (p0.y + bA.y * gs) + xlA.y;
                oA.z = x0A.z * (p1.x + bA.z * gs) + xlA.z;
                oA.w = x0A.w * (p1.y + bA.w * gs) + xlA.w;
                *reinterpret_cast<float4*>(sXL + r * D + dA) = oA;
            }
        }
    }

    __syncthreads();
    {
        const float4* src = reinterpret_cast<const float4*>(sXL);
        float4* dst = reinterpret_cast<float4*>(out + (size_t)row0 * D);
        for (int i = tid; i < ROWS * D / 4; i += THREADS) dst[i] = src[i];
    }
}

extern "C" void kernel_launch(void* const* d_in, const int* in_sizes, int n_in,
                              void* d_out, int out_size) {
    const float* x    = (const float*)d_in[0];
    const float* Vs   = (const float*)d_in[1];
    const float* Cs   = (const float*)d_in[2];
    const float* Us   = (const float*)d_in[3];
    const float* bias = (const float*)d_in[4];
    const float* gate = (const float*)d_in[5];
    float* out = (float*)d_out;

    const int prep_total = CROSS * D * EL + E * D;
    prep_kernel<<<(prep_total + 255) / 256, 256>>>(Us, gate);

    int rows = in_sizes[0] / D;
    int grid = rows / ROWS;

    cudaFuncSetAttribute(dcn_kernel,
                         cudaFuncAttributeMaxDynamicSharedMemorySize, SMEM_BYTES);
    dcn_kernel<<<grid, THREADS, SMEM_BYTES>>>(x, Vs, Cs, bias, out);
}

// round 4
// speedup vs baseline: 1.0525x; 1.0525x over previous
#include <cuda_runtime.h>
#include <math.h>

#define D      512
#define LR     64
#define E      4
#define EL     256      // E * LR
#define CROSS  3
#define ROWS   64       // rows per CTA
#define THREADS 512
#define KB     16       // k-block per stage

typedef unsigned long long u64;

// Scratch for transposed U weights: w2t[i][d][el] = Us[i][e][d][l], el = e*64+l
__device__ float g_w2t[CROSS * D * EL];
// Transposed gate: gwt[e][d] = gate_w[d][e]
__device__ float g_gwt[E * D];

__global__ void prep_kernel(const float* __restrict__ Us,
                            const float* __restrict__ gate_w) {
    int idx = blockIdx.x * blockDim.x + threadIdx.x;
    const int NW = CROSS * D * EL;
    if (idx < NW) {
        int i   = idx / (D * EL);
        int rem = idx % (D * EL);
        int d   = rem / EL;
        int el  = rem % EL;
        int e   = el / LR;
        int l   = el % LR;
        g_w2t[idx] = Us[((i * E + e) * D + d) * LR + l];
    } else if (idx < NW + E * D) {
        int j = idx - NW;
        int e = j / D, d = j % D;
        g_gwt[j] = gate_w[d * E + e];
    }
}

__device__ __forceinline__ float4 ld4(const float* p) {
    return *reinterpret_cast<const float4*>(p);
}
__device__ __forceinline__ ulonglong2 ld2u64(const float* p) {
    return *reinterpret_cast<const ulonglong2*>(p);
}
__device__ __forceinline__ void ffma2(u64& acc, u64 a, u64 b) {
    asm("fma.rn.f32x2 %0, %1, %2, %0;" : "+l"(acc) : "l"(a), "l"(b));
}
__device__ __forceinline__ u64 pack2(float x) {
    u64 r;
    asm("mov.b64 %0, {%1, %1};" : "=l"(r) : "f"(x));
    return r;
}
__device__ __forceinline__ float2 unpack2(u64 v) {
    float2 r;
    asm("mov.b64 {%0, %1}, %2;" : "=f"(r.x), "=f"(r.y) : "l"(v));
    return r;
}
__device__ __forceinline__ float fast_tanh(float x) {
    asm("tanh.approx.f32 %0, %0;" : "+f"(x));
    return x;
}

// Shared-memory GEMM with packed f32x2 FMA.
// 16 warps: warp w covers rows (w&7)*8..+8 and cols (w>>3)*128..+128.
// Lane covers 4 cols (2 packed pairs) x 8 rows -> acc2[8][2].
// Weights staged KB=16 deep in sW[KB][EL], written by all 512 threads.
// BD = block-diagonal C-phase: X k-offset depends on the e-block of the columns.
template<int KTOT, int XS, bool BD>
__device__ __forceinline__ void gemm_acc(
    const float* __restrict__ Wg, int ws,
    const float* __restrict__ sX, float* __restrict__ sW,
    u64 acc2[8][2], int tid)
{
    const int warp = tid >> 5, lane = tid & 31;
    const int r0 = (warp & 7) * 8;
    const int cA = (warp >> 3) * 128 + lane * 4;
    const int oA = BD ? ((cA >> 6) * LR) : 0;

    // weight staging: thread t handles col = t & 255, k-half = (t >> 8) * 8
    const int wcol = tid & 255;
    const int kh   = (tid >> 8) * 8;
    const float* gp = Wg + wcol * ws + kh;

    // prefetch first weight block
    float4 wa = ld4(gp + 0);
    float4 wb = ld4(gp + 4);

    #pragma unroll 1
    for (int kb = 0; kb < KTOT / KB; ++kb) {
        __syncthreads();                       // prior consumers of sW done
        sW[(kh+0)*EL + wcol] = wa.x; sW[(kh+1)*EL + wcol] = wa.y;
        sW[(kh+2)*EL + wcol] = wa.z; sW[(kh+3)*EL + wcol] = wa.w;
        sW[(kh+4)*EL + wcol] = wb.x; sW[(kh+5)*EL + wcol] = wb.y;
        sW[(kh+6)*EL + wcol] = wb.z; sW[(kh+7)*EL + wcol] = wb.w;
        if (kb + 1 < KTOT / KB) {              // overlap next global read w/ compute
            wa = ld4(gp + (kb + 1) * KB);
            wb = ld4(gp + (kb + 1) * KB + 4);
        }
        __syncthreads();

        #pragma unroll
        for (int h = 0; h < 4; ++h) {
            float4 xA[8];
            #pragma unroll
            for (int i = 0; i < 8; ++i)
                xA[i] = ld4(sX + (r0 + i) * XS + oA + kb * KB + h * 4);
            #pragma unroll
            for (int kk = 0; kk < 4; ++kk) {
                ulonglong2 wA = ld2u64(sW + (h * 4 + kk) * EL + cA);
                #pragma unroll
                for (int i = 0; i < 8; ++i) {
                    u64 xp = pack2((&xA[i].x)[kk]);
                    ffma2(acc2[i][0], xp, wA.x);
                    ffma2(acc2[i][1], xp, wA.y);
                }
            }
        }
    }
}

#define ZERO_ACC(acc2)                        \
    _Pragma("unroll")                         \
    for (int zi = 0; zi < 8; ++zi)            \
        _Pragma("unroll")                     \
        for (int zj = 0; zj < 2; ++zj)        \
            acc2[zi][zj] = 0ull;

// smem floats: sXL 64*512, sACT 64*256, sW 16*256, sG 64*4, sGS 64
#define SMEM_FLOATS (ROWS * D + ROWS * EL + KB * EL + ROWS * E + ROWS)
#define SMEM_BYTES  (SMEM_FLOATS * 4)

__global__ void __launch_bounds__(THREADS, 1)
dcn_kernel(const float* __restrict__ x,
           const float* __restrict__ Vs,
           const float* __restrict__ Cs,
           const float* __restrict__ bias,
           float* __restrict__ out)
{
    extern __shared__ float smem[];
    float* sXL  = smem;                    // [ROWS][D]
    float* sACT = sXL  + ROWS * D;         // [ROWS][EL]
    float* sW   = sACT + ROWS * EL;        // [KB][EL]
    float* sG   = sW   + KB * EL;          // [ROWS][E]
    float* sGS  = sG   + ROWS * E;         // [ROWS]

    const int tid  = threadIdx.x;
    const int bid  = blockIdx.x;
    const int row0 = bid * ROWS;
    const int warp = tid >> 5, lane = tid & 31;
    const int r0 = (warp & 7) * 8;
    const int cA = (warp >> 3) * 128 + lane * 4;

    // Load x tile into sXL
    {
        const float4* src = reinterpret_cast<const float4*>(x + (size_t)row0 * D);
        float4* dst = reinterpret_cast<float4*>(sXL);
        for (int i = tid; i < ROWS * D / 4; i += THREADS) dst[i] = src[i];
    }

    u64 acc2[8][2];

    for (int layer = 0; layer < CROSS; ++layer) {
        __syncthreads();   // sXL (prev layer epilogue / initial load) visible

        // ---- gate: g[r][e] = dot(x_l[r], gate_w[:,e]) ----
        if (tid < ROWS * E) {
            int r = tid >> 2, e = tid & 3;
            const float* xr = sXL + r * D;
            const float* gw = g_gwt + e * D;
            float g = 0.f;
            #pragma unroll 8
            for (int k = 0; k < D; k += 4) {
                float4 xv = ld4(xr + k);
                float4 wv = ld4(gw + k);
                g += xv.x * wv.x + xv.y * wv.y + xv.z * wv.z + xv.w * wv.w;
            }
            sG[tid] = g;
        }
        __syncthreads();
        if (tid < ROWS)
            sGS[tid] = sG[tid * 4] + sG[tid * 4 + 1] + sG[tid * 4 + 2] + sG[tid * 4 + 3];
        // (ordered by the sync inside the first gemm_acc iteration)

        // ---- V phase: v = tanh(Vs[i] @ x_l)  [64 x 256] ----
        ZERO_ACC(acc2);
        gemm_acc<D, D, false>(Vs + (size_t)layer * EL * D, D, sXL, sW, acc2, tid);
        #pragma unroll
        for (int i = 0; i < 8; ++i) {
            float2 p0 = unpack2(acc2[i][0]), p1 = unpack2(acc2[i][1]);
            float4 va = make_float4(fast_tanh(p0.x), fast_tanh(p0.y),
                                    fast_tanh(p1.x), fast_tanh(p1.y));
            *reinterpret_cast<float4*>(sACT + (r0 + i) * EL + cA) = va;
        }

        // ---- C phase (block diagonal): c' = g_e * tanh(Cs[i,e] @ v_e) ----
        ZERO_ACC(acc2);
        gemm_acc<LR, EL, true>(Cs + (size_t)layer * EL * LR, LR, sACT, sW, acc2, tid);
        __syncthreads();   // all reads of v complete before overwrite
        {
            const int eA = cA >> 6;
            #pragma unroll
            for (int i = 0; i < 8; ++i) {
                float ga = sG[(r0 + i) * 4 + eA];
                float2 p0 = unpack2(acc2[i][0]), p1 = unpack2(acc2[i][1]);
                float4 ca = make_float4(ga * fast_tanh(p0.x), ga * fast_tanh(p0.y),
                                        ga * fast_tanh(p1.x), ga * fast_tanh(p1.y));
                *reinterpret_cast<float4*>(sACT + (r0 + i) * EL + cA) = ca;
            }
        }

        // ---- U phase (two 256-col halves): x_l += x0*(U@c' + bias*sum_g) ----
        for (int half = 0; half < 2; ++half) {
            ZERO_ACC(acc2);
            gemm_acc<EL, EL, false>(
                g_w2t + (size_t)layer * D * EL + (size_t)half * 256 * EL,
                EL, sACT, sW, acc2, tid);
            #pragma unroll
            for (int i = 0; i < 8; ++i) {
                int r  = r0 + i;
                float gs = sGS[r];
                int dA = half * 256 + cA;
                float2 p0 = unpack2(acc2[i][0]), p1 = unpack2(acc2[i][1]);
                float4 bA  = ld4(bias + layer * D + dA);
                float4 x0A = ld4(x + (size_t)(row0 + r) * D + dA);
                float4 xlA = ld4(sXL + r * D + dA);
                float4 oA;
                oA.x = x0A.x * (p0.x + bA.x * gs) + xlA.x;
                oA.y = x0A.y * (p0.y + bA.y * gs) + xlA.y;
                oA.z = x0A.z * (p1.x + bA.z * gs) + xlA.z;
                oA.w = x0A.w * (p1.y + bA.w * gs) + xlA.w;
                *reinterpret_cast<float4*>(sXL + r * D + dA) = oA;
            }
        }
    }

    __syncthreads();
    {
        const float4* src = reinterpret_cast<const float4*>(sXL);
        float4* dst = reinterpret_cast<float4*>(out + (size_t)row0 * D);
        for (int i = tid; i < ROWS * D / 4; i += THREADS) dst[i] = src[i];
    }
}

extern "C" void kernel_launch(void* const* d_in, const int* in_sizes, int n_in,
                              void* d_out, int out_size) {
    const float* x    = (const float*)d_in[0];
    const float* Vs   = (const float*)d_in[1];
    const float* Cs   = (const float*)d_in[2];
    const float* Us   = (const float*)d_in[3];
    const float* bias = (const float*)d_in[4];
    const float* gate = (const float*)d_in[5];
    float* out = (float*)d_out;

    const int prep_total = CROSS * D * EL + E * D;
    prep_kernel<<<(prep_total + 255) / 256, 256>>>(Us, gate);

    int rows = in_sizes[0] / D;
    int grid = rows / ROWS;

    cudaFuncSetAttribute(dcn_kernel,
                         cudaFuncAttributeMaxDynamicSharedMemorySize, SMEM_BYTES);
    dcn_kernel<<<grid, THREADS, SMEM_BYTES>>>(x, Vs, Cs, bias, out);
}

// round 6
// speedup vs baseline: 2.2675x; 2.1544x over previous
#include <cuda_runtime.h>
#include <cuda_bf16.h>
#include <stdint.h>

#define CROSS   3
#define THREADS 256

// ---------------- prepped weight blobs (smem-image layout, swizzled) ----------
// B tile image: [256 n][64 k] bf16, rowstride 128B, offset = n*128 + ((2k)^((n&7)<<4))
__device__ __align__(16) __nv_bfloat16 gVB[CROSS * 8 * 2 * 16384];   // [L][chunk][split]
__device__ __align__(16) __nv_bfloat16 gCB[CROSS * 2 * 16384];       // [L][split]
__device__ __align__(16) __nv_bfloat16 gUB[CROSS * 2 * 4 * 2 * 16384]; // [L][half][chunk][split]
// gate plane image: [8 n][512 k] bf16, rowstride 1024B
__device__ __align__(16) __nv_bfloat16 gGB[2 * 4096];                // [split]

__device__ __forceinline__ __nv_bfloat16 bsplit(float w, int s) {
    __nv_bfloat16 h = __float2bfloat16(w);
    if (s == 0) return h;
    return __float2bfloat16(w - __bfloat162float(h));
}

__global__ void prep_kernel(const float* __restrict__ Vs,
                            const float* __restrict__ Cs,
                            const float* __restrict__ Us,
                            const float* __restrict__ gw) {
    int idx = blockIdx.x * 256 + threadIdx.x;
    const int NV = CROSS * 8 * 2 * 16384;
    const int NC = CROSS * 2 * 16384;
    const int NU = CROSS * 2 * 4 * 2 * 16384;
    const int NG = 2 * 4096;
    if (idx < NV) {
        int t = idx;
        int L = t / (8 * 2 * 16384); t %= 8 * 2 * 16384;
        int c = t / (2 * 16384);     t %= 2 * 16384;
        int s = t / 16384;           t %= 16384;
        int n = t >> 6, k = t & 63;
        float w = Vs[(size_t)(L * 256 + n) * 512 + c * 64 + k];
        gVB[(((L * 8 + c) * 2 + s) << 14) + ((n * 128 + ((2 * k) ^ ((n & 7) << 4))) >> 1)] = bsplit(w, s);
        return;
    }
    idx -= NV;
    if (idx < NC) {
        int t = idx;
        int L = t / (2 * 16384); t %= 2 * 16384;
        int s = t / 16384;       t %= 16384;
        int n = t >> 6, k = t & 63;
        float w = Cs[(size_t)L * 16384 + n * 64 + k];
        gCB[((L * 2 + s) << 14) + ((n * 128 + ((2 * k) ^ ((n & 7) << 4))) >> 1)] = bsplit(w, s);
        return;
    }
    idx -= NC;
    if (idx < NU) {
        int t = idx;
        int L = t / (16 * 16384); t %= 16 * 16384;
        int h = t / (8 * 16384);  t %= 8 * 16384;
        int c = t / (2 * 16384);  t %= 2 * 16384;
        int s = t / 16384;        t %= 16384;
        int n = t >> 6, k = t & 63;
        float w = Us[((size_t)(L * 4 + c) * 512 + h * 256 + n) * 64 + k];
        gUB[((((L * 2 + h) * 4 + c) * 2 + s) << 14) + ((n * 128 + ((2 * k) ^ ((n & 7) << 4))) >> 1)] = bsplit(w, s);
        return;
    }
    idx -= NU;
    if (idx < NG) {
        int t = idx;
        int s = t / 4096; t %= 4096;
        int n = t >> 9, k = t & 511;
        float w = (n < 4) ? gw[k * 4 + n] : 0.f;
        gGB[(s << 12) + ((n * 1024 + ((2 * k) ^ ((n & 7) << 4))) >> 1)] = bsplit(w, s);
    }
}

// ---------------- warp-level primitives ----------------
__device__ __forceinline__ uint32_t s2u(const void* p) {
    uint32_t a;
    asm("{ .reg .u64 t; cvta.to.shared.u64 t, %1; cvt.u32.u64 %0, t; }" : "=r"(a) : "l"(p));
    return a;
}
__device__ __forceinline__ void ldsm4(uint32_t r[4], uint32_t addr) {
    asm volatile("ldmatrix.sync.aligned.m8n8.x4.shared.b16 {%0,%1,%2,%3}, [%4];"
                 : "=r"(r[0]), "=r"(r[1]), "=r"(r[2]), "=r"(r[3]) : "r"(addr));
}
__device__ __forceinline__ void ldsm2(uint32_t r[2], uint32_t addr) {
    asm volatile("ldmatrix.sync.aligned.m8n8.x2.shared.b16 {%0,%1}, [%2];"
                 : "=r"(r[0]), "=r"(r[1]) : "r"(addr));
}
__device__ __forceinline__ void mma_bf16(float d[4], const uint32_t a[4], const uint32_t b0, const uint32_t b1) {
    asm volatile("mma.sync.aligned.m16n8k16.row.col.f32.bf16.bf16.f32 "
                 "{%0,%1,%2,%3}, {%4,%5,%6,%7}, {%8,%9}, {%0,%1,%2,%3};"
                 : "+f"(d[0]), "+f"(d[1]), "+f"(d[2]), "+f"(d[3])
                 : "r"(a[0]), "r"(a[1]), "r"(a[2]), "r"(a[3]), "r"(b0), "r"(b1));
}
__device__ __forceinline__ float fast_tanh(float x) {
    asm("tanh.approx.f32 %0, %0;" : "+f"(x));
    return x;
}
__device__ __forceinline__ void split2(float a, float b, uint32_t& hw, uint32_t& mw) {
    __nv_bfloat16 h0 = __float2bfloat16(a), h1 = __float2bfloat16(b);
    __nv_bfloat16 m0 = __float2bfloat16(a - __bfloat162float(h0));
    __nv_bfloat16 m1 = __float2bfloat16(b - __bfloat162float(h1));
    hw = (uint32_t)__bfloat16_as_ushort(h0) | ((uint32_t)__bfloat16_as_ushort(h1) << 16);
    mw = (uint32_t)__bfloat16_as_ushort(m0) | ((uint32_t)__bfloat16_as_ushort(m1) << 16);
}
__device__ __forceinline__ float bflo(uint32_t w) {
    return __bfloat162float(__ushort_as_bfloat16((unsigned short)(w & 0xFFFF)));
}
__device__ __forceinline__ float bfhi(uint32_t w) {
    return __bfloat162float(__ushort_as_bfloat16((unsigned short)(w >> 16)));
}
__device__ __forceinline__ void copy16(char* dst, const char* src, int bytes, int tid) {
    const float4* s = (const float4*)src;
    float4* d = (float4*)dst;
    for (int i = tid; i < bytes / 16; i += THREADS) d[i] = s[i];
}

// acc[rowfrag 2][n16 tile 4][n8 block 2][4]; warp tile = 32 rows x 64 cols.
// A plane: smem bf16 [rows][K] rowstride ars bytes, swizzled. B tile: [256][64], rs=128.
template<bool USE_AM>
__device__ __forceinline__ void mma_stage(
    uint32_t aHi, uint32_t aMid, uint32_t ars, uint32_t bB,
    int rowbase, int nbase, int ka0 /*bytes*/,
    float (&acc)[2][4][2][4], int lane)
{
    const uint32_t lr = lane & 15;          // row within 16
    const uint32_t lk = (lane >> 4) << 4;   // 0 or 16 bytes
    #pragma unroll
    for (int s = 0; s < 4; ++s) {
        uint32_t kaB = (uint32_t)ka0 + s * 32;
        uint32_t kbB = s * 32;
        uint32_t b[4][4];
        #pragma unroll
        for (int t = 0; t < 4; ++t) {
            uint32_t n = (uint32_t)(nbase + t * 16) + lr;
            ldsm4(b[t], bB + n * 128 + ((kbB + lk) ^ ((n & 7) << 4)));
        }
        uint32_t ah[2][4], am[2][4];
        #pragma unroll
        for (int rf = 0; rf < 2; ++rf) {
            uint32_t r = (uint32_t)(rowbase + rf * 16) + lr;
            uint32_t off = r * ars + ((kaB + lk) ^ ((r & 7) << 4));
            ldsm4(ah[rf], aHi + off);
            if (USE_AM) ldsm4(am[rf], aMid + off);
        }
        #pragma unroll
        for (int rf = 0; rf < 2; ++rf)
            #pragma unroll
            for (int t = 0; t < 4; ++t) {
                mma_bf16(acc[rf][t][0], ah[rf], b[t][0], b[t][2]);
                mma_bf16(acc[rf][t][1], ah[rf], b[t][1], b[t][3]);
                if (USE_AM) {
                    mma_bf16(acc[rf][t][0], am[rf], b[t][0], b[t][2]);
                    mma_bf16(acc[rf][t][1], am[rf], b[t][1], b[t][3]);
                }
            }
    }
}

#define ZEROACC                                   \
    _Pragma("unroll") for (int zi = 0; zi < 2; ++zi)  \
    _Pragma("unroll") for (int zj = 0; zj < 4; ++zj)  \
    _Pragma("unroll") for (int zk = 0; zk < 2; ++zk)  \
    _Pragma("unroll") for (int zl = 0; zl < 4; ++zl) acc[zi][zj][zk][zl] = 0.f;

// smem byte offsets
#define O_XH 0
#define O_XM 65536
#define O_VH 131072
#define O_VM 163840
#define O_B  196608
#define O_G  229376
#define O_GS 230400
#define SMEM_BYTES 230656

__global__ void __launch_bounds__(THREADS, 1)
dcn_kernel(const float* __restrict__ x,
           const float* __restrict__ bias,
           float* __restrict__ out)
{
    extern __shared__ char sm[];
    const uint32_t sb = s2u(sm);
    const int tid = threadIdx.x;
    const int w = tid >> 5, lane = tid & 31;
    const int row0 = blockIdx.x * 64;
    const int rowbase = (w & 1) * 32;
    const int cg = w >> 1;             // 0..3
    const int nbase = cg * 64;

    const uint32_t aXH = sb + O_XH, aXM = sb + O_XM;
    const uint32_t aVH = sb + O_VH, aVM = sb + O_VM;
    const uint32_t aB  = sb + O_B;
    float* sG  = (float*)(sm + O_G);
    float* sGS = (float*)(sm + O_GS);

    // ---- init: x -> hi/mid planes ----
    for (int i = tid; i < 64 * 256; i += THREADS) {
        int r = i >> 8, kp = i & 255;
        float2 v = *(const float2*)(x + (size_t)(row0 + r) * 512 + 2 * kp);
        uint32_t hw, mw;
        split2(v.x, v.y, hw, mw);
        uint32_t off = (uint32_t)r * 1024 + (((uint32_t)(4 * kp)) ^ (((uint32_t)r & 7) << 4));
        *(uint32_t*)(sm + O_XH + off) = hw;
        *(uint32_t*)(sm + O_XM + off) = mw;
    }

    float acc[2][4][2][4];

    #pragma unroll 1
    for (int L = 0; L < CROSS; ++L) {
        __syncthreads();
        // ---- gate ----
        copy16(sm + O_B, (const char*)gGB, 16384, tid);
        __syncthreads();
        if (w < 4) {
            float ga[4] = {0.f, 0.f, 0.f, 0.f};
            const uint32_t lr = lane & 15;
            const uint32_t lk = (lane >> 4) << 4;
            #pragma unroll 4
            for (int s = 0; s < 32; ++s) {
                uint32_t kb = s * 32;
                uint32_t r = (uint32_t)(w * 16) + lr;
                uint32_t aoff = r * 1024 + ((kb + lk) ^ ((r & 7) << 4));
                uint32_t ah[4], am[4];
                ldsm4(ah, aXH + aoff);
                ldsm4(am, aXM + aoff);
                uint32_t bn = lane & 7;
                uint32_t bk = kb + (((lane >> 3) & 1) << 4);
                uint32_t boff = bn * 1024 + (bk ^ ((bn & 7) << 4));
                uint32_t bh[2], bm[2];
                ldsm2(bh, aB + boff);
                ldsm2(bm, aB + 8192 + boff);
                mma_bf16(ga, ah, bh[0], bh[1]);
                mma_bf16(ga, am, bh[0], bh[1]);
                mma_bf16(ga, ah, bm[0], bm[1]);
            }
            int c0 = (lane & 3) * 2;
            if (c0 < 4) {
                int r1 = w * 16 + (lane >> 2);
                sG[r1 * 4 + c0] = ga[0];       sG[r1 * 4 + c0 + 1] = ga[1];
                sG[(r1 + 8) * 4 + c0] = ga[2]; sG[(r1 + 8) * 4 + c0 + 1] = ga[3];
            }
        }
        __syncthreads();
        if (tid < 64)
            sGS[tid] = sG[tid * 4] + sG[tid * 4 + 1] + sG[tid * 4 + 2] + sG[tid * 4 + 3];

        // ---- V: v = tanh(Vs @ x_l), K=512 in 8 chunks ----
        ZEROACC;
        #pragma unroll 1
        for (int c = 0; c < 8; ++c) {
            copy16(sm + O_B, (const char*)gVB + (size_t)((L * 8 + c) * 2 + 0) * 32768, 32768, tid);
            __syncthreads();
            mma_stage<true>(aXH, aXM, 1024, aB, rowbase, nbase, c * 128, acc, lane);
            __syncthreads();
            copy16(sm + O_B, (const char*)gVB + (size_t)((L * 8 + c) * 2 + 1) * 32768, 32768, tid);
            __syncthreads();
            mma_stage<false>(aXH, aXM, 1024, aB, rowbase, nbase, c * 128, acc, lane);
            __syncthreads();
        }
        // V epilogue -> sVh/sVm
        #pragma unroll
        for (int rf = 0; rf < 2; ++rf)
        #pragma unroll
        for (int t = 0; t < 4; ++t)
        #pragma unroll
        for (int nb = 0; nb < 2; ++nb) {
            float* d = acc[rf][t][nb];
            int n = nbase + t * 16 + nb * 8 + (lane & 3) * 2;
            #pragma unroll
            for (int rr = 0; rr < 2; ++rr) {
                int r = rowbase + rf * 16 + (lane >> 2) + rr * 8;
                float v0 = fast_tanh(d[rr * 2 + 0]);
                float v1 = fast_tanh(d[rr * 2 + 1]);
                uint32_t hw, mw;
                split2(v0, v1, hw, mw);
                uint32_t off = (uint32_t)r * 512 + (((uint32_t)(2 * n)) ^ (((uint32_t)r & 7) << 4));
                *(uint32_t*)(sm + O_VH + off) = hw;
                *(uint32_t*)(sm + O_VM + off) = mw;
            }
        }

        // ---- C: block-diagonal, warp = expert cg; K window = cg*64..+63 ----
        ZEROACC;
        copy16(sm + O_B, (const char*)gCB + (size_t)(L * 2 + 0) * 32768, 32768, tid);
        __syncthreads();
        mma_stage<true>(aVH, aVM, 512, aB, rowbase, nbase, cg * 128, acc, lane);
        __syncthreads();
        copy16(sm + O_B, (const char*)gCB + (size_t)(L * 2 + 1) * 32768, 32768, tid);
        __syncthreads();
        mma_stage<false>(aVH, aVM, 512, aB, rowbase, nbase, cg * 128, acc, lane);
        __syncthreads();
        // C epilogue: c' = g_e * tanh -> overwrite sVh/sVm
        #pragma unroll
        for (int rf = 0; rf < 2; ++rf)
        #pragma unroll
        for (int t = 0; t < 4; ++t)
        #pragma unroll
        for (int nb = 0; nb < 2; ++nb) {
            float* d = acc[rf][t][nb];
            int n = nbase + t * 16 + nb * 8 + (lane & 3) * 2;
            #pragma unroll
            for (int rr = 0; rr < 2; ++rr) {
                int r = rowbase + rf * 16 + (lane >> 2) + rr * 8;
                float g = sG[r * 4 + cg];
                float v0 = g * fast_tanh(d[rr * 2 + 0]);
                float v1 = g * fast_tanh(d[rr * 2 + 1]);
                uint32_t hw, mw;
                split2(v0, v1, hw, mw);
                uint32_t off = (uint32_t)r * 512 + (((uint32_t)(2 * n)) ^ (((uint32_t)r & 7) << 4));
                *(uint32_t*)(sm + O_VH + off) = hw;
                *(uint32_t*)(sm + O_VM + off) = mw;
            }
        }

        // ---- U: two 256-d halves, K=256 in 4 chunks; fused combine epilogue ----
        #pragma unroll 1
        for (int h = 0; h < 2; ++h) {
            ZEROACC;
            #pragma unroll 1
            for (int c = 0; c < 4; ++c) {
                copy16(sm + O_B, (const char*)gUB + (size_t)((((L * 2 + h) * 4 + c) * 2) + 0) * 32768, 32768, tid);
                __syncthreads();
                mma_stage<true>(aVH, aVM, 512, aB, rowbase, nbase, c * 128, acc, lane);
                __syncthreads();
                copy16(sm + O_B, (const char*)gUB + (size_t)((((L * 2 + h) * 4 + c) * 2) + 1) * 32768, 32768, tid);
                __syncthreads();
                mma_stage<false>(aVH, aVM, 512, aB, rowbase, nbase, c * 128, acc, lane);
                __syncthreads();
            }
            // epilogue: out = x0*(u + bias*gs) + xl
            #pragma unroll
            for (int rf = 0; rf < 2; ++rf)
            #pragma unroll
            for (int t = 0; t < 4; ++t)
            #pragma unroll
            for (int nb = 0; nb < 2; ++nb) {
                float* d = acc[rf][t][nb];
                int dc = h * 256 + nbase + t * 16 + nb * 8 + (lane & 3) * 2;
                float2 bv = *(const float2*)(bias + L * 512 + dc);
                #pragma unroll
                for (int rr = 0; rr < 2; ++rr) {
                    int r = rowbase + rf * 16 + (lane >> 2) + rr * 8;
                    float gs = sGS[r];
                    float2 x0 = *(const float2*)(x + (size_t)(row0 + r) * 512 + dc);
                    uint32_t off = (uint32_t)r * 1024 + (((uint32_t)(2 * dc)) ^ (((uint32_t)r & 7) << 4));
                    uint32_t xh = *(uint32_t*)(sm + O_XH + off);
                    uint32_t xm = *(uint32_t*)(sm + O_XM + off);
                    float xl0 = bflo(xh) + bflo(xm);
                    float xl1 = bfhi(xh) + bfhi(xm);
                    float o0 = x0.x * (d[rr * 2 + 0] + bv.x * gs) + xl0;
                    float o1 = x0.y * (d[rr * 2 + 1] + bv.y * gs) + xl1;
                    if (L == CROSS - 1) {
                        float2 ov = make_float2(o0, o1);
                        *(float2*)(out + (size_t)(row0 + r) * 512 + dc) = ov;
                    } else {
                        uint32_t hw, mw;
                        split2(o0, o1, hw, mw);
                        *(uint32_t*)(sm + O_XH + off) = hw;
                        *(uint32_t*)(sm + O_XM + off) = mw;
                    }
                }
            }
        }
    }
}

extern "C" void kernel_launch(void* const* d_in, const int* in_sizes, int n_in,
                              void* d_out, int out_size) {
    const float* x    = (const float*)d_in[0];
    const float* Vs   = (const float*)d_in[1];
    const float* Cs   = (const float*)d_in[2];
    const float* Us   = (const float*)d_in[3];
    const float* bias = (const float*)d_in[4];
    const float* gate = (const float*)d_in[5];
    float* out = (float*)d_out;

    const int total = CROSS*8*2*16384 + CROSS*2*16384 + CROSS*2*4*2*16384 + 2*4096;
    prep_kernel<<<(total + 255) / 256, 256>>>(Vs, Cs, Us, gate);

    int rows = in_sizes[0] / 512;
    int grid = rows / 64;

    cudaFuncSetAttribute(dcn_kernel, cudaFuncAttributeMaxDynamicSharedMemorySize, SMEM_BYTES);
    dcn_kernel<<<grid, THREADS, SMEM_BYTES>>>(x, bias, out);
}

// round 7
// speedup vs baseline: 2.6313x; 1.1605x over previous
#include <cuda_runtime.h>
#include <cuda_bf16.h>
#include <stdint.h>

#define CROSS   3
#define THREADS 512

// ---------------- prepped weight blobs (smem-image layout, swizzled) ----------
// B tile image: [256 n][64 k] bf16, rowstride 128B, offset = n*128 + ((2k)^((n&7)<<4))
__device__ __align__(16) __nv_bfloat16 gVB[CROSS * 8 * 2 * 16384];   // [L][chunk][split]
__device__ __align__(16) __nv_bfloat16 gCB[CROSS * 2 * 16384];       // [L][split]
__device__ __align__(16) __nv_bfloat16 gUB[CROSS * 2 * 4 * 2 * 16384]; // [L][half][chunk][split]
// gate plane image: [8 n][512 k] bf16, rowstride 1024B
__device__ __align__(16) __nv_bfloat16 gGB[2 * 4096];                // [split]

__device__ __forceinline__ __nv_bfloat16 bsplit(float w, int s) {
    __nv_bfloat16 h = __float2bfloat16(w);
    if (s == 0) return h;
    return __float2bfloat16(w - __bfloat162float(h));
}

__global__ void prep_kernel(const float* __restrict__ Vs,
                            const float* __restrict__ Cs,
                            const float* __restrict__ Us,
                            const float* __restrict__ gw) {
    int idx = blockIdx.x * 256 + threadIdx.x;
    const int NV = CROSS * 8 * 2 * 16384;
    const int NC = CROSS * 2 * 16384;
    const int NU = CROSS * 2 * 4 * 2 * 16384;
    const int NG = 2 * 4096;
    if (idx < NV) {
        int t = idx;
        int L = t / (8 * 2 * 16384); t %= 8 * 2 * 16384;
        int c = t / (2 * 16384);     t %= 2 * 16384;
        int s = t / 16384;           t %= 16384;
        int n = t >> 6, k = t & 63;
        float w = Vs[(size_t)(L * 256 + n) * 512 + c * 64 + k];
        gVB[(((L * 8 + c) * 2 + s) << 14) + ((n * 128 + ((2 * k) ^ ((n & 7) << 4))) >> 1)] = bsplit(w, s);
        return;
    }
    idx -= NV;
    if (idx < NC) {
        int t = idx;
        int L = t / (2 * 16384); t %= 2 * 16384;
        int s = t / 16384;       t %= 16384;
        int n = t >> 6, k = t & 63;
        float w = Cs[(size_t)L * 16384 + n * 64 + k];
        gCB[((L * 2 + s) << 14) + ((n * 128 + ((2 * k) ^ ((n & 7) << 4))) >> 1)] = bsplit(w, s);
        return;
    }
    idx -= NC;
    if (idx < NU) {
        int t = idx;
        int L = t / (16 * 16384); t %= 16 * 16384;
        int h = t / (8 * 16384);  t %= 8 * 16384;
        int c = t / (2 * 16384);  t %= 2 * 16384;
        int s = t / 16384;        t %= 16384;
        int n = t >> 6, k = t & 63;
        float w = Us[((size_t)(L * 4 + c) * 512 + h * 256 + n) * 64 + k];
        gUB[((((L * 2 + h) * 4 + c) * 2 + s) << 14) + ((n * 128 + ((2 * k) ^ ((n & 7) << 4))) >> 1)] = bsplit(w, s);
        return;
    }
    idx -= NU;
    if (idx < NG) {
        int t = idx;
        int s = t / 4096; t %= 4096;
        int n = t >> 9, k = t & 511;
        float w = (n < 4) ? gw[k * 4 + n] : 0.f;
        gGB[(s << 12) + ((n * 1024 + ((2 * k) ^ ((n & 7) << 4))) >> 1)] = bsplit(w, s);
    }
}

// ---------------- warp-level primitives ----------------
__device__ __forceinline__ uint32_t s2u(const void* p) {
    uint32_t a;
    asm("{ .reg .u64 t; cvta.to.shared.u64 t, %1; cvt.u32.u64 %0, t; }" : "=r"(a) : "l"(p));
    return a;
}
__device__ __forceinline__ void ldsm4(uint32_t r[4], uint32_t addr) {
    asm volatile("ldmatrix.sync.aligned.m8n8.x4.shared.b16 {%0,%1,%2,%3}, [%4];"
                 : "=r"(r[0]), "=r"(r[1]), "=r"(r[2]), "=r"(r[3]) : "r"(addr));
}
__device__ __forceinline__ void ldsm2(uint32_t r[2], uint32_t addr) {
    asm volatile("ldmatrix.sync.aligned.m8n8.x2.shared.b16 {%0,%1}, [%2];"
                 : "=r"(r[0]), "=r"(r[1]) : "r"(addr));
}
__device__ __forceinline__ void mma_bf16(float d[4], const uint32_t a[4], const uint32_t b0, const uint32_t b1) {
    asm volatile("mma.sync.aligned.m16n8k16.row.col.f32.bf16.bf16.f32 "
                 "{%0,%1,%2,%3}, {%4,%5,%6,%7}, {%8,%9}, {%0,%1,%2,%3};"
                 : "+f"(d[0]), "+f"(d[1]), "+f"(d[2]), "+f"(d[3])
                 : "r"(a[0]), "r"(a[1]), "r"(a[2]), "r"(a[3]), "r"(b0), "r"(b1));
}
__device__ __forceinline__ float fast_tanh(float x) {
    asm("tanh.approx.f32 %0, %0;" : "+f"(x));
    return x;
}
__device__ __forceinline__ void split2(float a, float b, uint32_t& hw, uint32_t& mw) {
    __nv_bfloat16 h0 = __float2bfloat16(a), h1 = __float2bfloat16(b);
    __nv_bfloat16 m0 = __float2bfloat16(a - __bfloat162float(h0));
    __nv_bfloat16 m1 = __float2bfloat16(b - __bfloat162float(h1));
    hw = (uint32_t)__bfloat16_as_ushort(h0) | ((uint32_t)__bfloat16_as_ushort(h1) << 16);
    mw = (uint32_t)__bfloat16_as_ushort(m0) | ((uint32_t)__bfloat16_as_ushort(m1) << 16);
}
__device__ __forceinline__ float bflo(uint32_t w) {
    return __bfloat162float(__ushort_as_bfloat16((unsigned short)(w & 0xFFFF)));
}
__device__ __forceinline__ float bfhi(uint32_t w) {
    return __bfloat162float(__ushort_as_bfloat16((unsigned short)(w >> 16)));
}
__device__ __forceinline__ void copy16(char* dst, const char* src, int bytes, int tid) {
    const float4* s = (const float4*)src;
    float4* d = (float4*)dst;
    for (int i = tid; i < bytes / 16; i += THREADS) d[i] = s[i];
}
// register prefetch of a 32KB B tile: 4 float4 per thread (512 threads)
__device__ __forceinline__ void ldpf(float4 pf[4], const char* src, int tid) {
    const float4* s = (const float4*)src;
    pf[0] = s[tid];        pf[1] = s[tid + 512];
    pf[2] = s[tid + 1024]; pf[3] = s[tid + 1536];
}
__device__ __forceinline__ void stpf(char* dst, const float4 pf[4], int tid) {
    float4* d = (float4*)dst;
    d[tid] = pf[0];        d[tid + 512] = pf[1];
    d[tid + 1024] = pf[2]; d[tid + 1536] = pf[3];
}

// pass p of a layer: V(0..15) -> C(16..17) -> U(18..33)
__device__ __forceinline__ const char* psrc(int L, int p) {
    if (p < 16) return (const char*)(gVB + ((size_t)((L * 8 + (p >> 1)) * 2 + (p & 1)) << 14));
    p -= 16;
    if (p < 2)  return (const char*)(gCB + ((size_t)(L * 2 + p) << 14));
    p -= 2;
    return (const char*)(gUB + ((size_t)((((L * 2 + (p >> 3)) * 4 + ((p >> 1) & 3)) * 2) + (p & 1)) << 14));
}

// warp tile = 32 rows x 32 cols. acc[rowfrag 2][n16 2][n8 2][4]
template<bool USE_AM>
__device__ __forceinline__ void mma_stage(
    uint32_t aHi, uint32_t aMid, uint32_t ars, uint32_t bB,
    int rowbase, int nbase, int ka0 /*bytes*/,
    float (&acc)[2][2][2][4], int lane)
{
    const uint32_t lr = lane & 15;
    const uint32_t lk = (lane >> 4) << 4;
    #pragma unroll
    for (int s = 0; s < 4; ++s) {
        uint32_t kaB = (uint32_t)ka0 + s * 32;
        uint32_t kbB = s * 32;
        uint32_t b[2][4];
        #pragma unroll
        for (int t = 0; t < 2; ++t) {
            uint32_t n = (uint32_t)(nbase + t * 16) + lr;
            ldsm4(b[t], bB + n * 128 + ((kbB + lk) ^ ((n & 7) << 4)));
        }
        uint32_t ah[2][4], am[2][4];
        #pragma unroll
        for (int rf = 0; rf < 2; ++rf) {
            uint32_t r = (uint32_t)(rowbase + rf * 16) + lr;
            uint32_t off = r * ars + ((kaB + lk) ^ ((r & 7) << 4));
            ldsm4(ah[rf], aHi + off);
            if (USE_AM) ldsm4(am[rf], aMid + off);
        }
        #pragma unroll
        for (int rf = 0; rf < 2; ++rf)
            #pragma unroll
            for (int t = 0; t < 2; ++t) {
                mma_bf16(acc[rf][t][0], ah[rf], b[t][0], b[t][2]);
                mma_bf16(acc[rf][t][1], ah[rf], b[t][1], b[t][3]);
                if (USE_AM) {
                    mma_bf16(acc[rf][t][0], am[rf], b[t][0], b[t][2]);
                    mma_bf16(acc[rf][t][1], am[rf], b[t][1], b[t][3]);
                }
            }
    }
}

#define ZEROACC                                       \
    _Pragma("unroll") for (int zi = 0; zi < 2; ++zi)  \
    _Pragma("unroll") for (int zj = 0; zj < 2; ++zj)  \
    _Pragma("unroll") for (int zk = 0; zk < 2; ++zk)  \
    _Pragma("unroll") for (int zl = 0; zl < 4; ++zl) acc[zi][zj][zk][zl] = 0.f;

// smem byte offsets
#define O_XH 0
#define O_XM 65536
#define O_VH 131072
#define O_VM 163840
#define O_B  196608
#define O_G  229376
#define O_GS 230400
#define SMEM_BYTES 230656

__global__ void __launch_bounds__(THREADS, 1)
dcn_kernel(const float* __restrict__ x,
           const float* __restrict__ bias,
           float* __restrict__ out)
{
    extern __shared__ char sm[];
    const uint32_t sb = s2u(sm);
    const int tid = threadIdx.x;
    const int w = tid >> 5, lane = tid & 31;
    const int row0 = blockIdx.x * 64;
    const int rowbase = (w & 1) * 32;
    const int cg = w >> 1;                 // 0..7 (32-col groups)
    const int nbase = cg * 32;
    const int ec = cg >> 1;                // expert for C phase

    const uint32_t aXH = sb + O_XH, aXM = sb + O_XM;
    const uint32_t aVH = sb + O_VH, aVM = sb + O_VM;
    const uint32_t aB  = sb + O_B;
    float* sG  = (float*)(sm + O_G);
    float* sGS = (float*)(sm + O_GS);

    // ---- init: x -> hi/mid planes ----
    for (int i = tid; i < 64 * 256; i += THREADS) {
        int r = i >> 8, kp = i & 255;
        float2 v = *(const float2*)(x + (size_t)(row0 + r) * 512 + 2 * kp);
        uint32_t hw, mw;
        split2(v.x, v.y, hw, mw);
        uint32_t off = (uint32_t)r * 1024 + (((uint32_t)(4 * kp)) ^ (((uint32_t)r & 7) << 4));
        *(uint32_t*)(sm + O_XH + off) = hw;
        *(uint32_t*)(sm + O_XM + off) = mw;
    }

    float acc[2][2][2][4];
    float4 pf[4];

    #pragma unroll 1
    for (int L = 0; L < CROSS; ++L) {
        __syncthreads();
        // ---- gate: copy plane, prefetch V pass0 during the copy+mma ----
        copy16(sm + O_B, (const char*)gGB, 16384, tid);
        ldpf(pf, psrc(L, 0), tid);
        __syncthreads();
        if (w < 4) {
            float ga[4] = {0.f, 0.f, 0.f, 0.f};
            const uint32_t lr = lane & 15;
            const uint32_t lk = (lane >> 4) << 4;
            #pragma unroll 4
            for (int s = 0; s < 32; ++s) {
                uint32_t kb = s * 32;
                uint32_t r = (uint32_t)(w * 16) + lr;
                uint32_t aoff = r * 1024 + ((kb + lk) ^ ((r & 7) << 4));
                uint32_t ah[4], am[4];
                ldsm4(ah, aXH + aoff);
                ldsm4(am, aXM + aoff);
                uint32_t bn = lane & 7;
                uint32_t bk = kb + (((lane >> 3) & 1) << 4);
                uint32_t boff = bn * 1024 + (bk ^ ((bn & 7) << 4));
                uint32_t bh[2], bm[2];
                ldsm2(bh, aB + boff);
                ldsm2(bm, aB + 8192 + boff);
                mma_bf16(ga, ah, bh[0], bh[1]);
                mma_bf16(ga, am, bh[0], bh[1]);
                mma_bf16(ga, ah, bm[0], bm[1]);
            }
            int c0 = (lane & 3) * 2;
            if (c0 < 4) {
                int r1 = w * 16 + (lane >> 2);
                sG[r1 * 4 + c0] = ga[0];       sG[r1 * 4 + c0 + 1] = ga[1];
                sG[(r1 + 8) * 4 + c0] = ga[2]; sG[(r1 + 8) * 4 + c0 + 1] = ga[3];
            }
        }
        __syncthreads();
        if (tid < 64)
            sGS[tid] = sG[tid * 4] + sG[tid * 4 + 1] + sG[tid * 4 + 2] + sG[tid * 4 + 3];

        int pi = 1;   // next pass index to prefetch

        // ---- V: K=512, 8 chunks x 2 splits ----
        ZEROACC;
        #pragma unroll 1
        for (int c = 0; c < 8; ++c) {
            #pragma unroll 1
            for (int s = 0; s < 2; ++s) {
                __syncthreads();
                stpf(sm + O_B, pf, tid);
                if (pi < 34) ldpf(pf, psrc(L, pi), tid);
                ++pi;
                __syncthreads();
                if (s == 0) mma_stage<true >(aXH, aXM, 1024, aB, rowbase, nbase, c * 128, acc, lane);
                else        mma_stage<false>(aXH, aXM, 1024, aB, rowbase, nbase, c * 128, acc, lane);
            }
        }
        // V epilogue -> VH/VM
        #pragma unroll
        for (int rf = 0; rf < 2; ++rf)
        #pragma unroll
        for (int t = 0; t < 2; ++t)
        #pragma unroll
        for (int nb = 0; nb < 2; ++nb) {
            float* d = acc[rf][t][nb];
            int n = nbase + t * 16 + nb * 8 + (lane & 3) * 2;
            #pragma unroll
            for (int rr = 0; rr < 2; ++rr) {
                int r = rowbase + rf * 16 + (lane >> 2) + rr * 8;
                float v0 = fast_tanh(d[rr * 2 + 0]);
                float v1 = fast_tanh(d[rr * 2 + 1]);
                uint32_t hw, mw;
                split2(v0, v1, hw, mw);
                uint32_t off = (uint32_t)r * 512 + (((uint32_t)(2 * n)) ^ (((uint32_t)r & 7) << 4));
                *(uint32_t*)(sm + O_VH + off) = hw;
                *(uint32_t*)(sm + O_VM + off) = mw;
            }
        }

        // ---- C: block diagonal ----
        ZEROACC;
        #pragma unroll 1
        for (int s = 0; s < 2; ++s) {
            __syncthreads();
            stpf(sm + O_B, pf, tid);
            ldpf(pf, psrc(L, pi), tid);
            ++pi;
            __syncthreads();
            if (s == 0) mma_stage<true >(aVH, aVM, 512, aB, rowbase, nbase, ec * 128, acc, lane);
            else        mma_stage<false>(aVH, aVM, 512, aB, rowbase, nbase, ec * 128, acc, lane);
        }
        __syncthreads();   // all V reads done before overwrite
        #pragma unroll
        for (int rf = 0; rf < 2; ++rf)
        #pragma unroll
        for (int t = 0; t < 2; ++t)
        #pragma unroll
        for (int nb = 0; nb < 2; ++nb) {
            float* d = acc[rf][t][nb];
            int n = nbase + t * 16 + nb * 8 + (lane & 3) * 2;
            #pragma unroll
            for (int rr = 0; rr < 2; ++rr) {
                int r = rowbase + rf * 16 + (lane >> 2) + rr * 8;
                float g = sG[r * 4 + ec];
                float v0 = g * fast_tanh(d[rr * 2 + 0]);
                float v1 = g * fast_tanh(d[rr * 2 + 1]);
                uint32_t hw, mw;
                split2(v0, v1, hw, mw);
                uint32_t off = (uint32_t)r * 512 + (((uint32_t)(2 * n)) ^ (((uint32_t)r & 7) << 4));
                *(uint32_t*)(sm + O_VH + off) = hw;
                *(uint32_t*)(sm + O_VM + off) = mw;
            }
        }

        // ---- U: two 256-d halves, fused combine ----
        #pragma unroll 1
        for (int h = 0; h < 2; ++h) {
            ZEROACC;
            #pragma unroll 1
            for (int c = 0; c < 4; ++c) {
                #pragma unroll 1
                for (int s = 0; s < 2; ++s) {
                    __syncthreads();
                    stpf(sm + O_B, pf, tid);
                    if (pi < 34) ldpf(pf, psrc(L, pi), tid);
                    ++pi;
                    __syncthreads();
                    if (s == 0) mma_stage<true >(aVH, aVM, 512, aB, rowbase, nbase, c * 128, acc, lane);
                    else        mma_stage<false>(aVH, aVM, 512, aB, rowbase, nbase, c * 128, acc, lane);
                }
            }
            // epilogue: out = x0*(u + bias*gs) + xl
            #pragma unroll
            for (int rf = 0; rf < 2; ++rf)
            #pragma unroll
            for (int t = 0; t < 2; ++t)
            #pragma unroll
            for (int nb = 0; nb < 2; ++nb) {
                float* d = acc[rf][t][nb];
                int dc = h * 256 + nbase + t * 16 + nb * 8 + (lane & 3) * 2;
                float2 bv = *(const float2*)(bias + L * 512 + dc);
                #pragma unroll
                for (int rr = 0; rr < 2; ++rr) {
                    int r = rowbase + rf * 16 + (lane >> 2) + rr * 8;
                    float gs = sGS[r];
                    float2 x0 = *(const float2*)(x + (size_t)(row0 + r) * 512 + dc);
                    uint32_t off = (uint32_t)r * 1024 + (((uint32_t)(2 * dc)) ^ (((uint32_t)r & 7) << 4));
                    uint32_t xh = *(uint32_t*)(sm + O_XH + off);
                    uint32_t xm = *(uint32_t*)(sm + O_XM + off);
                    float xl0 = bflo(xh) + bflo(xm);
                    float xl1 = bfhi(xh) + bfhi(xm);
                    float o0 = x0.x * (d[rr * 2 + 0] + bv.x * gs) + xl0;
                    float o1 = x0.y * (d[rr * 2 + 1] + bv.y * gs) + xl1;
                    if (L == CROSS - 1) {
                        *(float2*)(out + (size_t)(row0 + r) * 512 + dc) = make_float2(o0, o1);
                    } else {
                        uint32_t hw, mw;
                        split2(o0, o1, hw, mw);
                        *(uint32_t*)(sm + O_XH + off) = hw;
                        *(uint32_t*)(sm + O_XM + off) = mw;
                    }
                }
            }
        }
    }
}

extern "C" void kernel_launch(void* const* d_in, const int* in_sizes, int n_in,
                              void* d_out, int out_size) {
    const float* x    = (const float*)d_in[0];
    const float* Vs   = (const float*)d_in[1];
    const float* Cs   = (const float*)d_in[2];
    const float* Us   = (const float*)d_in[3];
    const float* bias = (const float*)d_in[4];
    const float* gate = (const float*)d_in[5];
    float* out = (float*)d_out;

    const int total = CROSS*8*2*16384 + CROSS*2*16384 + CROSS*2*4*2*16384 + 2*4096;
    prep_kernel<<<(total + 255) / 256, 256>>>(Vs, Cs, Us, gate);

    int rows = in_sizes[0] / 512;
    int grid = rows / 64;

    cudaFuncSetAttribute(dcn_kernel, cudaFuncAttributeMaxDynamicSharedMemorySize, SMEM_BYTES);
    dcn_kernel<<<grid, THREADS, SMEM_BYTES>>>(x, bias, out);
}

// round 8
// speedup vs baseline: 6.1527x; 2.3383x over previous
#include <cuda_runtime.h>
#include <cuda_fp16.h>
#include <stdint.h>

#define CROSS   3
#define THREADS 512

// ---------------- prepped fp16 weight blobs (smem-image layout, swizzled) -----
// B tile image: [256 n][64 k] fp16, rowstride 128B, offset = n*128 + ((2k)^((n&7)<<4))
__device__ __align__(16) __half gVB[CROSS * 8 * 16384];     // [L][chunk]
__device__ __align__(16) __half gCB[CROSS * 16384];         // [L]
__device__ __align__(16) __half gUB[CROSS * 2 * 4 * 16384]; // [L][half][chunk]
// gate plane image: [8 n][512 k] fp16, rowstride 1024B
__device__ __align__(16) __half gGB[4096];

__global__ void prep_kernel(const float* __restrict__ Vs,
                            const float* __restrict__ Cs,
                            const float* __restrict__ Us,
                            const float* __restrict__ gw) {
    int idx = blockIdx.x * 256 + threadIdx.x;
    const int NV = CROSS * 8 * 16384;
    const int NC = CROSS * 16384;
    const int NU = CROSS * 2 * 4 * 16384;
    const int NG = 4096;
    if (idx < NV) {
        int t = idx;
        int L = t / (8 * 16384); t %= 8 * 16384;
        int c = t / 16384;       t %= 16384;
        int n = t >> 6, k = t & 63;
        float w = Vs[(size_t)(L * 256 + n) * 512 + c * 64 + k];
        gVB[((size_t)(L * 8 + c) << 14) + ((n * 128 + ((2 * k) ^ ((n & 7) << 4))) >> 1)] = __float2half_rn(w);
        return;
    }
    idx -= NV;
    if (idx < NC) {
        int t = idx;
        int L = t / 16384; t %= 16384;
        int n = t >> 6, k = t & 63;
        float w = Cs[(size_t)L * 16384 + n * 64 + k];
        gCB[((size_t)L << 14) + ((n * 128 + ((2 * k) ^ ((n & 7) << 4))) >> 1)] = __float2half_rn(w);
        return;
    }
    idx -= NC;
    if (idx < NU) {
        int t = idx;
        int L = t / (8 * 16384); t %= 8 * 16384;
        int h = t / (4 * 16384); t %= 4 * 16384;
        int c = t / 16384;       t %= 16384;
        int n = t >> 6, k = t & 63;
        float w = Us[((size_t)(L * 4 + c) * 512 + h * 256 + n) * 64 + k];
        gUB[((size_t)((L * 2 + h) * 4 + c) << 14) + ((n * 128 + ((2 * k) ^ ((n & 7) << 4))) >> 1)] = __float2half_rn(w);
        return;
    }
    idx -= NU;
    if (idx < NG) {
        int n = idx >> 9, k = idx & 511;
        float w = (n < 4) ? gw[k * 4 + n] : 0.f;
        gGB[(n * 1024 + ((2 * k) ^ ((n & 7) << 4))) >> 1] = __float2half_rn(w);
    }
}

// ---------------- warp-level primitives ----------------
__device__ __forceinline__ uint32_t s2u(const void* p) {
    uint32_t a;
    asm("{ .reg .u64 t; cvta.to.shared.u64 t, %1; cvt.u32.u64 %0, t; }" : "=r"(a) : "l"(p));
    return a;
}
__device__ __forceinline__ void ldsm4(uint32_t r[4], uint32_t addr) {
    asm volatile("ldmatrix.sync.aligned.m8n8.x4.shared.b16 {%0,%1,%2,%3}, [%4];"
                 : "=r"(r[0]), "=r"(r[1]), "=r"(r[2]), "=r"(r[3]) : "r"(addr));
}
__device__ __forceinline__ void ldsm2(uint32_t r[2], uint32_t addr) {
    asm volatile("ldmatrix.sync.aligned.m8n8.x2.shared.b16 {%0,%1}, [%2];"
                 : "=r"(r[0]), "=r"(r[1]) : "r"(addr));
}
__device__ __forceinline__ void mma_f16(float d[4], const uint32_t a[4], const uint32_t b0, const uint32_t b1) {
    asm volatile("mma.sync.aligned.m16n8k16.row.col.f32.f16.f16.f32 "
                 "{%0,%1,%2,%3}, {%4,%5,%6,%7}, {%8,%9}, {%0,%1,%2,%3};"
                 : "+f"(d[0]), "+f"(d[1]), "+f"(d[2]), "+f"(d[3])
                 : "r"(a[0]), "r"(a[1]), "r"(a[2]), "r"(a[3]), "r"(b0), "r"(b1));
}
__device__ __forceinline__ float fast_tanh(float x) {
    asm("tanh.approx.f32 %0, %0;" : "+f"(x));
    return x;
}
__device__ __forceinline__ uint32_t packh(float a, float b) {
    __half2 p = __floats2half2_rn(a, b);
    return *(uint32_t*)&p;
}
__device__ __forceinline__ void split2h(float a, float b, uint32_t& hw, uint32_t& mw) {
    __half h0 = __float2half_rn(a), h1 = __float2half_rn(b);
    __half m0 = __float2half_rn(a - __half2float(h0));
    __half m1 = __float2half_rn(b - __half2float(h1));
    hw = (uint32_t)*(unsigned short*)&h0 | ((uint32_t)*(unsigned short*)&h1 << 16);
    mw = (uint32_t)*(unsigned short*)&m0 | ((uint32_t)*(unsigned short*)&m1 << 16);
}
__device__ __forceinline__ float hlo(uint32_t w) {
    unsigned short s = (unsigned short)(w & 0xFFFF);
    return __half2float(*(__half*)&s);
}
__device__ __forceinline__ float hhi(uint32_t w) {
    unsigned short s = (unsigned short)(w >> 16);
    return __half2float(*(__half*)&s);
}
__device__ __forceinline__ void copy16(char* dst, const char* src, int bytes, int tid) {
    const float4* s = (const float4*)src;
    float4* d = (float4*)dst;
    for (int i = tid; i < bytes / 16; i += THREADS) d[i] = s[i];
}
// register prefetch of a 32KB B tile: 4 float4 per thread (512 threads)
__device__ __forceinline__ void ldpf(float4 pf[4], const char* src, int tid) {
    const float4* s = (const float4*)src;
    pf[0] = s[tid];        pf[1] = s[tid + 512];
    pf[2] = s[tid + 1024]; pf[3] = s[tid + 1536];
}
__device__ __forceinline__ void stpf(char* dst, const float4 pf[4], int tid) {
    float4* d = (float4*)dst;
    d[tid] = pf[0];        d[tid + 512] = pf[1];
    d[tid + 1024] = pf[2]; d[tid + 1536] = pf[3];
}

// pass p of a layer: V(0..7) -> C(8) -> U(9..16)
__device__ __forceinline__ const char* psrc(int L, int p) {
    if (p < 8)  return (const char*)(gVB + ((size_t)(L * 8 + p) << 14));
    if (p == 8) return (const char*)(gCB + ((size_t)L << 14));
    int q = p - 9;
    return (const char*)(gUB + ((size_t)((L * 2 + (q >> 2)) * 4 + (q & 3)) << 14));
}

// warp tile = 32 rows x 32 cols. acc[rowfrag 2][n16 2][n8 2][4]. Single fp16 pass.
__device__ __forceinline__ void mma_stage(
    uint32_t aA, uint32_t ars, uint32_t bB,
    int rowbase, int nbase, int ka0 /*bytes*/,
    float (&acc)[2][2][2][4], int lane)
{
    const uint32_t lr = lane & 15;
    const uint32_t lk = (lane >> 4) << 4;
    #pragma unroll
    for (int s = 0; s < 4; ++s) {
        uint32_t kaB = (uint32_t)ka0 + s * 32;
        uint32_t kbB = s * 32;
        uint32_t b[2][4];
        #pragma unroll
        for (int t = 0; t < 2; ++t) {
            uint32_t n = (uint32_t)(nbase + t * 16) + lr;
            ldsm4(b[t], bB + n * 128 + ((kbB + lk) ^ ((n & 7) << 4)));
        }
        uint32_t a[2][4];
        #pragma unroll
        for (int rf = 0; rf < 2; ++rf) {
            uint32_t r = (uint32_t)(rowbase + rf * 16) + lr;
            ldsm4(a[rf], aA + r * ars + ((kaB + lk) ^ ((r & 7) << 4)));
        }
        #pragma unroll
        for (int rf = 0; rf < 2; ++rf)
            #pragma unroll
            for (int t = 0; t < 2; ++t) {
                mma_f16(acc[rf][t][0], a[rf], b[t][0], b[t][2]);
                mma_f16(acc[rf][t][1], a[rf], b[t][1], b[t][3]);
            }
    }
}

#define ZEROACC                                       \
    _Pragma("unroll") for (int zi = 0; zi < 2; ++zi)  \
    _Pragma("unroll") for (int zj = 0; zj < 2; ++zj)  \
    _Pragma("unroll") for (int zk = 0; zk < 2; ++zk)  \
    _Pragma("unroll") for (int zl = 0; zl < 4; ++zl) acc[zi][zj][zk][zl] = 0.f;

// smem byte offsets
#define O_XH 0          // x_l hi plane  [64][512] fp16 (64KB)
#define O_XM 65536      // x_l mid plane (64KB)
#define O_V  131072     // v / c' plane  [64][256] fp16 (32KB)
#define O_B0 163840     // B ping (32KB)
#define O_B1 196608     // B pong (32KB)
#define O_G  229376     // sG [64][4] f32
#define O_GS 230400     // sGS [64] f32
#define SMEM_BYTES 230656

// one pipelined pass: store prefetched tile, prefetch next, barrier, mma
#define PASS(aA, ars, ka0, p, npL, npP)                                   \
    do {                                                                  \
        stpf(sm + (((p) & 1) ? O_B1 : O_B0), pf, tid);                    \
        if ((npL) < CROSS) ldpf(pf, psrc((npL), (npP)), tid);             \
        __syncthreads();                                                  \
        mma_stage((aA), (ars), sb + (((p) & 1) ? O_B1 : O_B0),            \
                  rowbase, nbase, (ka0), acc, lane);                      \
    } while (0)

__global__ void __launch_bounds__(THREADS, 1)
dcn_kernel(const float* __restrict__ x,
           const float* __restrict__ bias,
           float* __restrict__ out)
{
    extern __shared__ char sm[];
    const uint32_t sb = s2u(sm);
    const int tid = threadIdx.x;
    const int w = tid >> 5, lane = tid & 31;
    const int row0 = blockIdx.x * 64;
    const int rowbase = (w & 1) * 32;
    const int cg = w >> 1;                 // 0..7 (32-col groups)
    const int nbase = cg * 32;
    const int ec = cg >> 1;                // expert for C phase

    const uint32_t aXH = sb + O_XH;
    const uint32_t aV  = sb + O_V;
    float* sG  = (float*)(sm + O_G);
    float* sGS = (float*)(sm + O_GS);

    // ---- init: x -> fp16 hi/mid planes ----
    for (int i = tid; i < 64 * 256; i += THREADS) {
        int r = i >> 8, kp = i & 255;
        float2 v = *(const float2*)(x + (size_t)(row0 + r) * 512 + 2 * kp);
        uint32_t hw, mw;
        split2h(v.x, v.y, hw, mw);
        uint32_t off = (uint32_t)r * 1024 + (((uint32_t)(4 * kp)) ^ (((uint32_t)r & 7) << 4));
        *(uint32_t*)(sm + O_XH + off) = hw;
        *(uint32_t*)(sm + O_XM + off) = mw;
    }

    float acc[2][2][2][4];
    float4 pf[4];
    ldpf(pf, psrc(0, 0), tid);

    #pragma unroll 1
    for (int L = 0; L < CROSS; ++L) {
        // ---- gate: stage plane into B1, mma on 4 warps ----
        copy16(sm + O_B1, (const char*)gGB, 8192, tid);
        __syncthreads();   // also orders prev-layer epilogue writes of XH/XM
        if (w < 4) {
            float ga[4] = {0.f, 0.f, 0.f, 0.f};
            const uint32_t lr = lane & 15;
            const uint32_t lk = (lane >> 4) << 4;
            #pragma unroll 4
            for (int s = 0; s < 32; ++s) {
                uint32_t kb = s * 32;
                uint32_t r = (uint32_t)(w * 16) + lr;
                uint32_t ah[4];
                ldsm4(ah, aXH + r * 1024 + ((kb + lk) ^ ((r & 7) << 4)));
                uint32_t bn = lane & 7;
                uint32_t bk = kb + (((lane >> 3) & 1) << 4);
                uint32_t bh[2];
                ldsm2(bh, sb + O_B1 + bn * 1024 + (bk ^ ((bn & 7) << 4)));
                mma_f16(ga, ah, bh[0], bh[1]);
            }
            int c0 = (lane & 3) * 2;
            if (c0 < 4) {
                int r1 = w * 16 + (lane >> 2);
                sG[r1 * 4 + c0] = ga[0];       sG[r1 * 4 + c0 + 1] = ga[1];
                sG[(r1 + 8) * 4 + c0] = ga[2]; sG[(r1 + 8) * 4 + c0 + 1] = ga[3];
            }
        }
        __syncthreads();
        if (tid < 64)
            sGS[tid] = sG[tid * 4] + sG[tid * 4 + 1] + sG[tid * 4 + 2] + sG[tid * 4 + 3];

        // ---- V: v = tanh(Vs @ x_l), K=512 in 8 single passes ----
        ZEROACC;
        #pragma unroll 1
        for (int c = 0; c < 8; ++c)
            PASS(aXH, 1024, c * 128, c, L, c + 1);
        // V epilogue -> V plane (fp16 single)
        #pragma unroll
        for (int rf = 0; rf < 2; ++rf)
        #pragma unroll
        for (int t = 0; t < 2; ++t)
        #pragma unroll
        for (int nb = 0; nb < 2; ++nb) {
            float* d = acc[rf][t][nb];
            int n = nbase + t * 16 + nb * 8 + (lane & 3) * 2;
            #pragma unroll
            for (int rr = 0; rr < 2; ++rr) {
                int r = rowbase + rf * 16 + (lane >> 2) + rr * 8;
                uint32_t off = (uint32_t)r * 512 + (((uint32_t)(2 * n)) ^ (((uint32_t)r & 7) << 4));
                *(uint32_t*)(sm + O_V + off) =
                    packh(fast_tanh(d[rr * 2 + 0]), fast_tanh(d[rr * 2 + 1]));
            }
        }

        // ---- C: block diagonal, one pass ----
        ZEROACC;
        PASS(aV, 512, ec * 128, 8, L, 9);
        __syncthreads();   // all C-mma reads of V done before overwrite
        #pragma unroll
        for (int rf = 0; rf < 2; ++rf)
        #pragma unroll
        for (int t = 0; t < 2; ++t)
        #pragma unroll
        for (int nb = 0; nb < 2; ++nb) {
            float* d = acc[rf][t][nb];
            int n = nbase + t * 16 + nb * 8 + (lane & 3) * 2;
            #pragma unroll
            for (int rr = 0; rr < 2; ++rr) {
                int r = rowbase + rf * 16 + (lane >> 2) + rr * 8;
                float g = sG[r * 4 + ec];
                uint32_t off = (uint32_t)r * 512 + (((uint32_t)(2 * n)) ^ (((uint32_t)r & 7) << 4));
                *(uint32_t*)(sm + O_V + off) =
                    packh(g * fast_tanh(d[rr * 2 + 0]), g * fast_tanh(d[rr * 2 + 1]));
            }
        }

        // ---- U: two 256-d halves x 4 chunks; fused combine epilogue ----
        #pragma unroll 1
        for (int h = 0; h < 2; ++h) {
            ZEROACC;
            #pragma unroll 1
            for (int c = 0; c < 4; ++c) {
                int p = 9 + h * 4 + c;
                int npL = (p + 1 < 17) ? L : L + 1;
                int npP = (p + 1 < 17) ? p + 1 : 0;
                PASS(aV, 512, c * 128, p, npL, npP);
            }
            // epilogue: out = x0*(u + bias*gs) + x_l
            #pragma unroll
            for (int rf = 0; rf < 2; ++rf)
            #pragma unroll
            for (int t = 0; t < 2; ++t)
            #pragma unroll
            for (int nb = 0; nb < 2; ++nb) {
                float* d = acc[rf][t][nb];
                int dc = h * 256 + nbase + t * 16 + nb * 8 + (lane & 3) * 2;
                float2 bv = *(const float2*)(bias + L * 512 + dc);
                #pragma unroll
                for (int rr = 0; rr < 2; ++rr) {
                    int r = rowbase + rf * 16 + (lane >> 2) + rr * 8;
                    float gs = sGS[r];
                    float2 x0 = *(const float2*)(x + (size_t)(row0 + r) * 512 + dc);
                    uint32_t off = (uint32_t)r * 1024 + (((uint32_t)(2 * dc)) ^ (((uint32_t)r & 7) << 4));
                    uint32_t xh = *(uint32_t*)(sm + O_XH + off);
                    uint32_t xm = *(uint32_t*)(sm + O_XM + off);
                    float xl0 = hlo(xh) + hlo(xm);
                    float xl1 = hhi(xh) + hhi(xm);
                    float o0 = x0.x * (d[rr * 2 + 0] + bv.x * gs) + xl0;
                    float o1 = x0.y * (d[rr * 2 + 1] + bv.y * gs) + xl1;
                    if (L == CROSS - 1) {
                        *(float2*)(out + (size_t)(row0 + r) * 512 + dc) = make_float2(o0, o1);
                    } else {
                        uint32_t hw, mw;
                        split2h(o0, o1, hw, mw);
                        *(uint32_t*)(sm + O_XH + off) = hw;
                        *(uint32_t*)(sm + O_XM + off) = mw;
                    }
                }
            }
        }
    }
}

extern "C" void kernel_launch(void* const* d_in, const int* in_sizes, int n_in,
                              void* d_out, int out_size) {
    const float* x    = (const float*)d_in[0];
    const float* Vs   = (const float*)d_in[1];
    const float* Cs   = (const float*)d_in[2];
    const float* Us   = (const float*)d_in[3];
    const float* bias = (const float*)d_in[4];
    const float* gate = (const float*)d_in[5];
    float* out = (float*)d_out;

    const int total = CROSS*8*16384 + CROSS*16384 + CROSS*2*4*16384 + 4096;
    prep_kernel<<<(total + 255) / 256, 256>>>(Vs, Cs, Us, gate);

    int rows = in_sizes[0] / 512;
    int grid = rows / 64;

    cudaFuncSetAttribute(dcn_kernel, cudaFuncAttributeMaxDynamicSharedMemorySize, SMEM_BYTES);
    dcn_kernel<<<grid, THREADS, SMEM_BYTES>>>(x, bias, out);
}

// round 9
// speedup vs baseline: 6.6489x; 1.0806x over previous
#include <cuda_runtime.h>
#include <cuda_fp16.h>
#include <stdint.h>

#define CROSS   3
#define THREADS 512
#define NPASS   (CROSS * 17)

// ---------------- prepped fp16 weight blobs (smem-image layout, swizzled) -----
// B tile image: [256 n][64 k] fp16, rowstride 128B, offset = n*128 + ((2k)^((n&7)<<4))
__device__ __align__(16) __half gVB[CROSS * 8 * 16384];     // [L][chunk]
__device__ __align__(16) __half gCB[CROSS * 16384];         // [L]
__device__ __align__(16) __half gUB[CROSS * 2 * 4 * 16384]; // [L][half][chunk]
// gate plane image: [8 n][512 k] fp16, rowstride 1024B
__device__ __align__(16) __half gGB[4096];

__global__ void prep_kernel(const float* __restrict__ Vs,
                            const float* __restrict__ Cs,
                            const float* __restrict__ Us,
                            const float* __restrict__ gw) {
    int idx = blockIdx.x * 256 + threadIdx.x;
    const int NV = CROSS * 8 * 16384;
    const int NC = CROSS * 16384;
    const int NU = CROSS * 2 * 4 * 16384;
    const int NG = 4096;
    if (idx < NV) {
        int t = idx;
        int L = t / (8 * 16384); t %= 8 * 16384;
        int c = t / 16384;       t %= 16384;
        int n = t >> 6, k = t & 63;
        float w = Vs[(size_t)(L * 256 + n) * 512 + c * 64 + k];
        gVB[((size_t)(L * 8 + c) << 14) + ((n * 128 + ((2 * k) ^ ((n & 7) << 4))) >> 1)] = __float2half_rn(w);
        return;
    }
    idx -= NV;
    if (idx < NC) {
        int t = idx;
        int L = t / 16384; t %= 16384;
        int n = t >> 6, k = t & 63;
        float w = Cs[(size_t)L * 16384 + n * 64 + k];
        gCB[((size_t)L << 14) + ((n * 128 + ((2 * k) ^ ((n & 7) << 4))) >> 1)] = __float2half_rn(w);
        return;
    }
    idx -= NC;
    if (idx < NU) {
        int t = idx;
        int L = t / (8 * 16384); t %= 8 * 16384;
        int h = t / (4 * 16384); t %= 4 * 16384;
        int c = t / 16384;       t %= 16384;
        int n = t >> 6, k = t & 63;
        float w = Us[((size_t)(L * 4 + c) * 512 + h * 256 + n) * 64 + k];
        gUB[((size_t)((L * 2 + h) * 4 + c) << 14) + ((n * 128 + ((2 * k) ^ ((n & 7) << 4))) >> 1)] = __float2half_rn(w);
        return;
    }
    idx -= NU;
    if (idx < NG) {
        int n = idx >> 9, k = idx & 511;
        float w = (n < 4) ? gw[k * 4 + n] : 0.f;
        gGB[(n * 1024 + ((2 * k) ^ ((n & 7) << 4))) >> 1] = __float2half_rn(w);
    }
}

// ---------------- warp-level primitives ----------------
__device__ __forceinline__ uint32_t s2u(const void* p) {
    uint32_t a;
    asm("{ .reg .u64 t; cvta.to.shared.u64 t, %1; cvt.u32.u64 %0, t; }" : "=r"(a) : "l"(p));
    return a;
}
__device__ __forceinline__ void ldsm4(uint32_t r[4], uint32_t addr) {
    asm volatile("ldmatrix.sync.aligned.m8n8.x4.shared.b16 {%0,%1,%2,%3}, [%4];"
                 : "=r"(r[0]), "=r"(r[1]), "=r"(r[2]), "=r"(r[3]) : "r"(addr));
}
__device__ __forceinline__ void ldsm2(uint32_t r[2], uint32_t addr) {
    asm volatile("ldmatrix.sync.aligned.m8n8.x2.shared.b16 {%0,%1}, [%2];"
                 : "=r"(r[0]), "=r"(r[1]) : "r"(addr));
}
__device__ __forceinline__ void mma_f16(float d[4], const uint32_t a[4], const uint32_t b0, const uint32_t b1) {
    asm volatile("mma.sync.aligned.m16n8k16.row.col.f32.f16.f16.f32 "
                 "{%0,%1,%2,%3}, {%4,%5,%6,%7}, {%8,%9}, {%0,%1,%2,%3};"
                 : "+f"(d[0]), "+f"(d[1]), "+f"(d[2]), "+f"(d[3])
                 : "r"(a[0]), "r"(a[1]), "r"(a[2]), "r"(a[3]), "r"(b0), "r"(b1));
}
__device__ __forceinline__ float fast_tanh(float x) {
    asm("tanh.approx.f32 %0, %0;" : "+f"(x));
    return x;
}
__device__ __forceinline__ uint32_t packh(float a, float b) {
    __half2 p = __floats2half2_rn(a, b);
    return *(uint32_t*)&p;
}
__device__ __forceinline__ void split2h(float a, float b, uint32_t& hw, uint32_t& mw) {
    __half h0 = __float2half_rn(a), h1 = __float2half_rn(b);
    __half m0 = __float2half_rn(a - __half2float(h0));
    __half m1 = __float2half_rn(b - __half2float(h1));
    hw = (uint32_t)*(unsigned short*)&h0 | ((uint32_t)*(unsigned short*)&h1 << 16);
    mw = (uint32_t)*(unsigned short*)&m0 | ((uint32_t)*(unsigned short*)&m1 << 16);
}
__device__ __forceinline__ float hlo(uint32_t w) {
    unsigned short s = (unsigned short)(w & 0xFFFF);
    return __half2float(*(__half*)&s);
}
__device__ __forceinline__ float hhi(uint32_t w) {
    unsigned short s = (unsigned short)(w >> 16);
    return __half2float(*(__half*)&s);
}
__device__ __forceinline__ void copy16(char* dst, const char* src, int bytes, int tid) {
    const float4* s = (const float4*)src;
    float4* d = (float4*)dst;
    for (int i = tid; i < bytes / 16; i += THREADS) d[i] = s[i];
}

// ---------------- cp.async staging ----------------
__device__ __forceinline__ void cpasync16(uint32_t saddr, const void* gptr) {
    asm volatile("cp.async.cg.shared.global [%0], [%1], 16;" :: "r"(saddr), "l"(gptr) : "memory");
}
#define CP_COMMIT() asm volatile("cp.async.commit_group;" ::: "memory")
#define CP_WAIT0()  asm volatile("cp.async.wait_group 0;"  ::: "memory")

// pass g (global, 0..50): layer L = g/17; within layer: V(0..7) -> C(8) -> U(9..16)
__device__ __forceinline__ const char* psrc_g(int g) {
    int L = g / 17;
    int p = g - L * 17;
    if (p < 8)  return (const char*)(gVB + ((size_t)(L * 8 + p) << 14));
    if (p == 8) return (const char*)(gCB + ((size_t)L << 14));
    int q = p - 9;
    return (const char*)(gUB + ((size_t)((L * 2 + (q >> 2)) * 4 + (q & 3)) << 14));
}
// stage a 32KB B tile asynchronously: 4 x 16B per thread
__device__ __forceinline__ void stage_async(uint32_t sdst, const char* gsrc, int tid) {
    #pragma unroll
    for (int i = 0; i < 4; ++i)
        cpasync16(sdst + (uint32_t)(tid + i * 512) * 16, gsrc + (size_t)(tid + i * 512) * 16);
    CP_COMMIT();
}

// warp tile = 32 rows x 32 cols. acc[rowfrag 2][n16 2][n8 2][4]. Single fp16 pass.
__device__ __forceinline__ void mma_stage(
    uint32_t aA, uint32_t ars, uint32_t bB,
    int rowbase, int nbase, int ka0 /*bytes*/,
    float (&acc)[2][2][2][4], int lane)
{
    const uint32_t lr = lane & 15;
    const uint32_t lk = (lane >> 4) << 4;
    #pragma unroll
    for (int s = 0; s < 4; ++s) {
        uint32_t kaB = (uint32_t)ka0 + s * 32;
        uint32_t kbB = s * 32;
        uint32_t b[2][4];
        #pragma unroll
        for (int t = 0; t < 2; ++t) {
            uint32_t n = (uint32_t)(nbase + t * 16) + lr;
            ldsm4(b[t], bB + n * 128 + ((kbB + lk) ^ ((n & 7) << 4)));
        }
        uint32_t a[2][4];
        #pragma unroll
        for (int rf = 0; rf < 2; ++rf) {
            uint32_t r = (uint32_t)(rowbase + rf * 16) + lr;
            ldsm4(a[rf], aA + r * ars + ((kaB + lk) ^ ((r & 7) << 4)));
        }
        #pragma unroll
        for (int rf = 0; rf < 2; ++rf)
            #pragma unroll
            for (int t = 0; t < 2; ++t) {
                mma_f16(acc[rf][t][0], a[rf], b[t][0], b[t][2]);
                mma_f16(acc[rf][t][1], a[rf], b[t][1], b[t][3]);
            }
    }
}

#define ZEROACC                                       \
    _Pragma("unroll") for (int zi = 0; zi < 2; ++zi)  \
    _Pragma("unroll") for (int zj = 0; zj < 2; ++zj)  \
    _Pragma("unroll") for (int zk = 0; zk < 2; ++zk)  \
    _Pragma("unroll") for (int zl = 0; zl < 4; ++zl) acc[zi][zj][zk][zl] = 0.f;

// smem byte offsets
#define O_XH 0          // x_l hi plane  [64][512] fp16 (64KB)
#define O_XM 65536      // x_l mid plane (64KB)
#define O_V  131072     // v / c' plane  [64][256] fp16 (32KB)
#define O_B0 163840     // B ping (32KB)
#define O_B1 196608     // B pong (32KB)
#define O_G  229376     // sG [64][4] f32
#define O_GS 230400     // sGS [64] f32
#define SMEM_BYTES 230656

#define BOFF(g) (((g) & 1) ? O_B1 : O_B0)

// pipelined pass: wait cp(g), barrier, kick cp(g+1), mma on buf(g)
#define PASS(aA, ars, ka0, g)                                                  \
    do {                                                                       \
        CP_WAIT0();                                                            \
        __syncthreads();                                                       \
        if ((g) + 1 < NPASS)                                                   \
            stage_async(sb + BOFF((g) + 1), psrc_g((g) + 1), tid);             \
        mma_stage((aA), (ars), sb + BOFF(g), rowbase, nbase, (ka0), acc, lane);\
    } while (0)

__global__ void __launch_bounds__(THREADS, 1)
dcn_kernel(const float* __restrict__ x,
           const float* __restrict__ bias,
           float* __restrict__ out)
{
    extern __shared__ char sm[];
    const uint32_t sb = s2u(sm);
    const int tid = threadIdx.x;
    const int w = tid >> 5, lane = tid & 31;
    const int row0 = blockIdx.x * 64;
    const int rowbase = (w & 1) * 32;
    const int cg = w >> 1;                 // 0..7 (32-col groups)
    const int nbase = cg * 32;
    const int ec = cg >> 1;                // expert for C phase

    const uint32_t aXH = sb + O_XH;
    const uint32_t aV  = sb + O_V;
    float* sG  = (float*)(sm + O_G);
    float* sGS = (float*)(sm + O_GS);

    // kick off the first B tile immediately
    stage_async(sb + BOFF(0), psrc_g(0), tid);

    // ---- init: x -> fp16 hi/mid planes ----
    for (int i = tid; i < 64 * 256; i += THREADS) {
        int r = i >> 8, kp = i & 255;
        float2 v = *(const float2*)(x + (size_t)(row0 + r) * 512 + 2 * kp);
        uint32_t hw, mw;
        split2h(v.x, v.y, hw, mw);
        uint32_t off = (uint32_t)r * 1024 + (((uint32_t)(4 * kp)) ^ (((uint32_t)r & 7) << 4));
        *(uint32_t*)(sm + O_XH + off) = hw;
        *(uint32_t*)(sm + O_XM + off) = mw;
    }

    float acc[2][2][2][4];

    #pragma unroll 1
    for (int L = 0; L < CROSS; ++L) {
        const int g0 = L * 17;
        const uint32_t gbo = BOFF(g0 + 1);   // buffer idle until cp(g0+1) is issued

        // ---- gate: stage plane into the idle buffer, mma on 4 warps ----
        __syncthreads();   // prev-layer mma reads + epilogue XH/XM writes settled
        copy16(sm + gbo, (const char*)gGB, 8192, tid);
        __syncthreads();
        if (w < 4) {
            float ga[4] = {0.f, 0.f, 0.f, 0.f};
            const uint32_t lr = lane & 15;
            const uint32_t lk = (lane >> 4) << 4;
            #pragma unroll 4
            for (int s = 0; s < 32; ++s) {
                uint32_t kb = s * 32;
                uint32_t r = (uint32_t)(w * 16) + lr;
                uint32_t ah[4];
                ldsm4(ah, aXH + r * 1024 + ((kb + lk) ^ ((r & 7) << 4)));
                uint32_t bn = lane & 7;
                uint32_t bk = kb + (((lane >> 3) & 1) << 4);
                uint32_t bh[2];
                ldsm2(bh, sb + gbo + bn * 1024 + (bk ^ ((bn & 7) << 4)));
                mma_f16(ga, ah, bh[0], bh[1]);
            }
            int c0 = (lane & 3) * 2;
            if (c0 < 4) {
                int r1 = w * 16 + (lane >> 2);
                sG[r1 * 4 + c0] = ga[0];       sG[r1 * 4 + c0 + 1] = ga[1];
                sG[(r1 + 8) * 4 + c0] = ga[2]; sG[(r1 + 8) * 4 + c0 + 1] = ga[3];
            }
        }
        __syncthreads();
        if (tid < 64)
            sGS[tid] = sG[tid * 4] + sG[tid * 4 + 1] + sG[tid * 4 + 2] + sG[tid * 4 + 3];

        // ---- V: v = tanh(Vs @ x_l), K=512 in 8 passes ----
        ZEROACC;
        #pragma unroll 1
        for (int c = 0; c < 8; ++c)
            PASS(aXH, 1024, c * 128, g0 + c);
        // V epilogue -> V plane
        #pragma unroll
        for (int rf = 0; rf < 2; ++rf)
        #pragma unroll
        for (int t = 0; t < 2; ++t)
        #pragma unroll
        for (int nb = 0; nb < 2; ++nb) {
            float* d = acc[rf][t][nb];
            int n = nbase + t * 16 + nb * 8 + (lane & 3) * 2;
            #pragma unroll
            for (int rr = 0; rr < 2; ++rr) {
                int r = rowbase + rf * 16 + (lane >> 2) + rr * 8;
                uint32_t off = (uint32_t)r * 512 + (((uint32_t)(2 * n)) ^ (((uint32_t)r & 7) << 4));
                *(uint32_t*)(sm + O_V + off) =
                    packh(fast_tanh(d[rr * 2 + 0]), fast_tanh(d[rr * 2 + 1]));
            }
        }

        // ---- C: block diagonal, one pass ----
        ZEROACC;
        PASS(aV, 512, ec * 128, g0 + 8);
        __syncthreads();   // all C-mma reads of V done before overwrite
        #pragma unroll
        for (int rf = 0; rf < 2; ++rf)
        #pragma unroll
        for (int t = 0; t < 2; ++t)
        #pragma unroll
        for (int nb = 0; nb < 2; ++nb) {
            float* d = acc[rf][t][nb];
            int n = nbase + t * 16 + nb * 8 + (lane & 3) * 2;
            #pragma unroll
            for (int rr = 0; rr < 2; ++rr) {
                int r = rowbase + rf * 16 + (lane >> 2) + rr * 8;
                float g = sG[r * 4 + ec];
                uint32_t off = (uint32_t)r * 512 + (((uint32_t)(2 * n)) ^ (((uint32_t)r & 7) << 4));
                *(uint32_t*)(sm + O_V + off) =
                    packh(g * fast_tanh(d[rr * 2 + 0]), g * fast_tanh(d[rr * 2 + 1]));
            }
        }

        // ---- U: two 256-d halves x 4 chunks; fused combine epilogue ----
        #pragma unroll 1
        for (int h = 0; h < 2; ++h) {
            ZEROACC;
            #pragma unroll 1
            for (int c = 0; c < 4; ++c)
                PASS(aV, 512, c * 128, g0 + 9 + h * 4 + c);
            // epilogue: out = x0*(u + bias*gs) + x_l
            #pragma unroll
            for (int rf = 0; rf < 2; ++rf)
            #pragma unroll
            for (int t = 0; t < 2; ++t)
            #pragma unroll
            for (int nb = 0; nb < 2; ++nb) {
                float* d = acc[rf][t][nb];
                int dc = h * 256 + nbase + t * 16 + nb * 8 + (lane & 3) * 2;
                float2 bv = *(const float2*)(bias + L * 512 + dc);
                #pragma unroll
                for (int rr = 0; rr < 2; ++rr) {
                    int r = rowbase + rf * 16 + (lane >> 2) + rr * 8;
                    float gs = sGS[r];
                    float2 x0 = *(const float2*)(x + (size_t)(row0 + r) * 512 + dc);
                    uint32_t off = (uint32_t)r * 1024 + (((uint32_t)(2 * dc)) ^ (((uint32_t)r & 7) << 4));
                    uint32_t xh = *(uint32_t*)(sm + O_XH + off);
                    uint32_t xm = *(uint32_t*)(sm + O_XM + off);
                    float xl0 = hlo(xh) + hlo(xm);
                    float xl1 = hhi(xh) + hhi(xm);
                    float o0 = x0.x * (d[rr * 2 + 0] + bv.x * gs) + xl0;
                    float o1 = x0.y * (d[rr * 2 + 1] + bv.y * gs) + xl1;
                    if (L == CROSS - 1) {
                        *(float2*)(out + (size_t)(row0 + r) * 512 + dc) = make_float2(o0, o1);
                    } else {
                        uint32_t hw, mw;
                        split2h(o0, o1, hw, mw);
                        *(uint32_t*)(sm + O_XH + off) = hw;
                        *(uint32_t*)(sm + O_XM + off) = mw;
                    }
                }
            }
        }
    }
}

extern "C" void kernel_launch(void* const* d_in, const int* in_sizes, int n_in,
                              void* d_out, int out_size) {
    const float* x    = (const float*)d_in[0];
    const float* Vs   = (const float*)d_in[1];
    const float* Cs   = (const float*)d_in[2];
    const float* Us   = (const float*)d_in[3];
    const float* bias = (const float*)d_in[4];
    const float* gate = (const float*)d_in[5];
    float* out = (float*)d_out;

    const int total = CROSS*8*16384 + CROSS*16384 + CROSS*2*4*16384 + 4096;
    prep_kernel<<<(total + 255) / 256, 256>>>(Vs, Cs, Us, gate);

    int rows = in_sizes[0] / 512;
    int grid = rows / 64;

    cudaFuncSetAttribute(dcn_kernel, cudaFuncAttributeMaxDynamicSharedMemorySize, SMEM_BYTES);
    dcn_kernel<<<grid, THREADS, SMEM_BYTES>>>(x, bias, out);
}

// round 10
// speedup vs baseline: 7.0817x; 1.0651x over previous
#include <cuda_runtime.h>
#include <cuda_fp16.h>
#include <stdint.h>

#define CROSS   3
#define THREADS 512
#define NPASS   (CROSS * 17)

// ---------------- contiguous prepped fp16 weight blob ----------------
// tile g (0..50) at gWT + g*16384 halfs; image: [256 n][64 k] fp16,
// rowstride 128B, offset = n*128 + ((2k)^((n&7)<<4)).
// per-layer order: V chunks 0..7, C, U h0c0..h0c3, U h1c0..h1c3.
__device__ __align__(16) __half gWT[NPASS * 16384];
// gate plane image: [8 n][512 k] fp16, rowstride 1024B
__device__ __align__(16) __half gGB[4096];

__global__ void prep_kernel(const float* __restrict__ Vs,
                            const float* __restrict__ Cs,
                            const float* __restrict__ Us,
                            const float* __restrict__ gw) {
    int idx = blockIdx.x * 256 + threadIdx.x;
    const int NW = NPASS * 16384;
    if (idx < NW) {
        int g = idx >> 14;
        int t = idx & 16383;
        int n = t >> 6, k = t & 63;
        int L = g / 17, p = g - L * 17;
        float w;
        if (p < 8) {
            w = Vs[(size_t)(L * 256 + n) * 512 + p * 64 + k];
        } else if (p == 8) {
            w = Cs[(size_t)L * 16384 + n * 64 + k];
        } else {
            int q = p - 9, h = q >> 2, c = q & 3;
            w = Us[((size_t)(L * 4 + c) * 512 + h * 256 + n) * 64 + k];
        }
        gWT[((size_t)g << 14) + ((n * 128 + ((2 * k) ^ ((n & 7) << 4))) >> 1)] = __float2half_rn(w);
        return;
    }
    idx -= NW;
    if (idx < 4096) {
        int n = idx >> 9, k = idx & 511;
        float w = (n < 4) ? gw[k * 4 + n] : 0.f;
        gGB[(n * 1024 + ((2 * k) ^ ((n & 7) << 4))) >> 1] = __float2half_rn(w);
    }
}

// ---------------- warp-level primitives ----------------
__device__ __forceinline__ uint32_t s2u(const void* p) {
    uint32_t a;
    asm("{ .reg .u64 t; cvta.to.shared.u64 t, %1; cvt.u32.u64 %0, t; }" : "=r"(a) : "l"(p));
    return a;
}
__device__ __forceinline__ void ldsm4(uint32_t r[4], uint32_t addr) {
    asm volatile("ldmatrix.sync.aligned.m8n8.x4.shared.b16 {%0,%1,%2,%3}, [%4];"
                 : "=r"(r[0]), "=r"(r[1]), "=r"(r[2]), "=r"(r[3]) : "r"(addr));
}
__device__ __forceinline__ void ldsm2(uint32_t r[2], uint32_t addr) {
    asm volatile("ldmatrix.sync.aligned.m8n8.x2.shared.b16 {%0,%1}, [%2];"
                 : "=r"(r[0]), "=r"(r[1]) : "r"(addr));
}
__device__ __forceinline__ void mma_f16(float d[4], const uint32_t a[4], const uint32_t b0, const uint32_t b1) {
    asm volatile("mma.sync.aligned.m16n8k16.row.col.f32.f16.f16.f32 "
                 "{%0,%1,%2,%3}, {%4,%5,%6,%7}, {%8,%9}, {%0,%1,%2,%3};"
                 : "+f"(d[0]), "+f"(d[1]), "+f"(d[2]), "+f"(d[3])
                 : "r"(a[0]), "r"(a[1]), "r"(a[2]), "r"(a[3]), "r"(b0), "r"(b1));
}
__device__ __forceinline__ float fast_tanh(float x) {
    asm("tanh.approx.f32 %0, %0;" : "+f"(x));
    return x;
}
__device__ __forceinline__ uint32_t packh(float a, float b) {
    __half2 p = __floats2half2_rn(a, b);
    return *(uint32_t*)&p;
}
__device__ __forceinline__ void split2h(float a, float b, uint32_t& hw, uint32_t& mw) {
    __half h0 = __float2half_rn(a), h1 = __float2half_rn(b);
    __half m0 = __float2half_rn(a - __half2float(h0));
    __half m1 = __float2half_rn(b - __half2float(h1));
    hw = (uint32_t)*(unsigned short*)&h0 | ((uint32_t)*(unsigned short*)&h1 << 16);
    mw = (uint32_t)*(unsigned short*)&m0 | ((uint32_t)*(unsigned short*)&m1 << 16);
}
__device__ __forceinline__ float hlo(uint32_t w) {
    unsigned short s = (unsigned short)(w & 0xFFFF);
    return __half2float(*(__half*)&s);
}
__device__ __forceinline__ float hhi(uint32_t w) {
    unsigned short s = (unsigned short)(w >> 16);
    return __half2float(*(__half*)&s);
}
__device__ __forceinline__ void copy16(char* dst, const char* src, int bytes, int tid) {
    const float4* s = (const float4*)src;
    float4* d = (float4*)dst;
    for (int i = tid; i < bytes / 16; i += THREADS) d[i] = s[i];
}

// ---------------- cp.async staging ----------------
__device__ __forceinline__ void cpasync16(uint32_t saddr, const void* gptr) {
    asm volatile("cp.async.cg.shared.global [%0], [%1], 16;" :: "r"(saddr), "l"(gptr) : "memory");
}
#define CP_COMMIT() asm volatile("cp.async.commit_group;" ::: "memory")
#define CP_WAIT0()  asm volatile("cp.async.wait_group 0;"  ::: "memory")

// stage a 32KB B tile asynchronously: 4 x 16B per thread
__device__ __forceinline__ void stage_async(uint32_t sdst, const char* gsrc, int tid) {
    #pragma unroll
    for (int i = 0; i < 4; ++i)
        cpasync16(sdst + (uint32_t)(tid + i * 512) * 16, gsrc + (size_t)(tid + i * 512) * 16);
    CP_COMMIT();
}

// warp tile = 32 rows x 32 cols. acc[rowfrag 2][n16 2][n8 2][4]. Single fp16 pass.
// All swizzle math pre-hoisted: addresses are base + kx[s].
__device__ __forceinline__ void mma_stage(
    uint32_t aB0, uint32_t aB1,           // A plane + ka0 + row offsets (rf 0/1)
    uint32_t bB0, uint32_t bB1,           // B buffer + n offsets (t 0/1)
    const uint32_t kx[4],
    float (&acc)[2][2][2][4])
{
    #pragma unroll
    for (int s = 0; s < 4; ++s) {
        uint32_t b0[4], b1[4], a0[4], a1[4];
        ldsm4(b0, bB0 + kx[s]);
        ldsm4(b1, bB1 + kx[s]);
        ldsm4(a0, aB0 + kx[s]);
        ldsm4(a1, aB1 + kx[s]);
        mma_f16(acc[0][0][0], a0, b0[0], b0[2]);
        mma_f16(acc[0][0][1], a0, b0[1], b0[3]);
        mma_f16(acc[0][1][0], a0, b1[0], b1[2]);
        mma_f16(acc[0][1][1], a0, b1[1], b1[3]);
        mma_f16(acc[1][0][0], a1, b0[0], b0[2]);
        mma_f16(acc[1][0][1], a1, b0[1], b0[3]);
        mma_f16(acc[1][1][0], a1, b1[0], b1[2]);
        mma_f16(acc[1][1][1], a1, b1[1], b1[3]);
    }
}

#define ZEROACC                                       \
    _Pragma("unroll") for (int zi = 0; zi < 2; ++zi)  \
    _Pragma("unroll") for (int zj = 0; zj < 2; ++zj)  \
    _Pragma("unroll") for (int zk = 0; zk < 2; ++zk)  \
    _Pragma("unroll") for (int zl = 0; zl < 4; ++zl) acc[zi][zj][zk][zl] = 0.f;

// smem byte offsets
#define O_XH 0          // x_l hi plane  [64][512] fp16 (64KB)
#define O_XM 65536      // x_l mid plane (64KB)
#define O_V  131072     // v / c' plane  [64][256] fp16 (32KB)
#define O_B0 163840     // B ping (32KB)
#define O_B1 196608     // B pong (32KB)
#define O_G  229376     // sG [64][4] f32
#define O_GS 230400     // sGS [64] f32
#define SMEM_BYTES 230656

#define BOFF(g) (((g) & 1) ? O_B1 : O_B0)

// pipelined pass: wait cp(g), barrier, kick cp(g+1), mma on buf(g)
#define PASS(aP0, aP1, ka0, g)                                                 \
    do {                                                                       \
        CP_WAIT0();                                                            \
        __syncthreads();                                                       \
        if ((g) + 1 < NPASS)                                                   \
            stage_async(sb + BOFF((g) + 1),                                    \
                        (const char*)gWT + ((size_t)((g) + 1) << 15), tid);    \
        mma_stage((aP0) + (ka0), (aP1) + (ka0),                                \
                  bN0 + BOFF(g), bN1 + BOFF(g), kx, acc);                      \
    } while (0)

__global__ void __launch_bounds__(THREADS, 1)
dcn_kernel(const float* __restrict__ x,
           const float* __restrict__ bias,
           float* __restrict__ out)
{
    extern __shared__ char sm[];
    const uint32_t sb = s2u(sm);
    const int tid = threadIdx.x;
    const int w = tid >> 5, lane = tid & 31;
    const int row0 = blockIdx.x * 64;
    const int rowbase = (w & 1) * 32;
    const int cg = w >> 1;                 // 0..7 (32-col groups)
    const int nbase = cg * 32;
    const int ec = cg >> 1;                // expert for C phase

    // ---- hoisted ldsm addressing (per-thread constants) ----
    const uint32_t lr = (uint32_t)(lane & 15);
    const uint32_t lk = (uint32_t)((lane >> 4) << 4);
    const uint32_t csw = (uint32_t)((lane & 7) << 4);
    uint32_t kx[4];
    #pragma unroll
    for (int s = 0; s < 4; ++s) kx[s] = ((uint32_t)(s * 32) + lk) ^ csw;
    // A plane row offsets (x_l plane: rowstride 1024; v plane: rowstride 512)
    const uint32_t aX0 = sb + O_XH + ((uint32_t)rowbase + 0  + lr) * 1024;
    const uint32_t aX1 = sb + O_XH + ((uint32_t)rowbase + 16 + lr) * 1024;
    const uint32_t aV0 = sb + O_V  + ((uint32_t)rowbase + 0  + lr) * 512;
    const uint32_t aV1 = sb + O_V  + ((uint32_t)rowbase + 16 + lr) * 512;
    // B tile n offsets (rowstride 128)
    const uint32_t bN0 = sb + ((uint32_t)nbase + 0  + lr) * 128;
    const uint32_t bN1 = sb + ((uint32_t)nbase + 16 + lr) * 128;

    float* sG  = (float*)(sm + O_G);
    float* sGS = (float*)(sm + O_GS);

    // kick off the first B tile immediately
    stage_async(sb + BOFF(0), (const char*)gWT, tid);

    // ---- init: x -> fp16 hi/mid planes ----
    for (int i = tid; i < 64 * 256; i += THREADS) {
        int r = i >> 8, kp = i & 255;
        float2 v = *(const float2*)(x + (size_t)(row0 + r) * 512 + 2 * kp);
        uint32_t hw, mw;
        split2h(v.x, v.y, hw, mw);
        uint32_t off = (uint32_t)r * 1024 + (((uint32_t)(4 * kp)) ^ (((uint32_t)r & 7) << 4));
        *(uint32_t*)(sm + O_XH + off) = hw;
        *(uint32_t*)(sm + O_XM + off) = mw;
    }

    float acc[2][2][2][4];

    #pragma unroll 1
    for (int L = 0; L < CROSS; ++L) {
        const int g0 = L * 17;
        const uint32_t gbo = BOFF(g0 + 1);   // buffer idle until cp(g0+1) is issued

        // ---- gate: stage plane into the idle buffer, mma on 4 warps ----
        __syncthreads();   // prev-layer mma reads + epilogue XH/XM writes settled
        copy16(sm + gbo, (const char*)gGB, 8192, tid);
        __syncthreads();
        if (w < 4) {
            float ga[4] = {0.f, 0.f, 0.f, 0.f};
            #pragma unroll 4
            for (int s = 0; s < 32; ++s) {
                uint32_t kb = s * 32;
                uint32_t r = (uint32_t)(w * 16) + lr;
                uint32_t ah[4];
                ldsm4(ah, sb + O_XH + r * 1024 + ((kb + lk) ^ ((r & 7) << 4)));
                uint32_t bn = lane & 7;
                uint32_t bk = kb + (((lane >> 3) & 1) << 4);
                uint32_t bh[2];
                ldsm2(bh, sb + gbo + bn * 1024 + (bk ^ ((bn & 7) << 4)));
                mma_f16(ga, ah, bh[0], bh[1]);
            }
            int c0 = (lane & 3) * 2;
            if (c0 < 4) {
                int r1 = w * 16 + (lane >> 2);
                sG[r1 * 4 + c0] = ga[0];       sG[r1 * 4 + c0 + 1] = ga[1];
                sG[(r1 + 8) * 4 + c0] = ga[2]; sG[(r1 + 8) * 4 + c0 + 1] = ga[3];
            }
        }
        // (sG visibility is covered by the first V pass's barrier)

        // ---- V: v = tanh(Vs @ x_l), K=512 in 8 passes ----
        ZEROACC;
        #pragma unroll 1
        for (int c = 0; c < 8; ++c)
            PASS(aX0, aX1, c * 128, g0 + c);
        // gate row-sums (sG visible since first V-pass barrier; consumed in U epi)
        if (tid < 64)
            sGS[tid] = sG[tid * 4] + sG[tid * 4 + 1] + sG[tid * 4 + 2] + sG[tid * 4 + 3];
        // V epilogue -> V plane
        #pragma unroll
        for (int rf = 0; rf < 2; ++rf)
        #pragma unroll
        for (int t = 0; t < 2; ++t)
        #pragma unroll
        for (int nb = 0; nb < 2; ++nb) {
            float* d = acc[rf][t][nb];
            int n = nbase + t * 16 + nb * 8 + (lane & 3) * 2;
            #pragma unroll
            for (int rr = 0; rr < 2; ++rr) {
                int r = rowbase + rf * 16 + (lane >> 2) + rr * 8;
                uint32_t off = (uint32_t)r * 512 + (((uint32_t)(2 * n)) ^ (((uint32_t)r & 7) << 4));
                *(uint32_t*)(sm + O_V + off) =
                    packh(fast_tanh(d[rr * 2 + 0]), fast_tanh(d[rr * 2 + 1]));
            }
        }

        // ---- C: block diagonal, one pass ----
        ZEROACC;
        PASS(aV0, aV1, ec * 128, g0 + 8);
        __syncthreads();   // all C-mma reads of V done before overwrite
        #pragma unroll
        for (int rf = 0; rf < 2; ++rf)
        #pragma unroll
        for (int t = 0; t < 2; ++t)
        #pragma unroll
        for (int nb = 0; nb < 2; ++nb) {
            float* d = acc[rf][t][nb];
            int n = nbase + t * 16 + nb * 8 + (lane & 3) * 2;
            #pragma unroll
            for (int rr = 0; rr < 2; ++rr) {
                int r = rowbase + rf * 16 + (lane >> 2) + rr * 8;
                float g = sG[r * 4 + ec];
                uint32_t off = (uint32_t)r * 512 + (((uint32_t)(2 * n)) ^ (((uint32_t)r & 7) << 4));
                *(uint32_t*)(sm + O_V + off) =
                    packh(g * fast_tanh(d[rr * 2 + 0]), g * fast_tanh(d[rr * 2 + 1]));
            }
        }

        // ---- U: two 256-d halves x 4 chunks; fused combine epilogue ----
        #pragma unroll 1
        for (int h = 0; h < 2; ++h) {
            ZEROACC;
            #pragma unroll 1
            for (int c = 0; c < 4; ++c)
                PASS(aV0, aV1, c * 128, g0 + 9 + h * 4 + c);
            // epilogue: out = x0*(u + bias*gs) + x_l
            #pragma unroll
            for (int rf = 0; rf < 2; ++rf)
            #pragma unroll
            for (int t = 0; t < 2; ++t)
            #pragma unroll
            for (int nb = 0; nb < 2; ++nb) {
                float* d = acc[rf][t][nb];
                int dc = h * 256 + nbase + t * 16 + nb * 8 + (lane & 3) * 2;
                float2 bv = *(const float2*)(bias + L * 512 + dc);
                #pragma unroll
                for (int rr = 0; rr < 2; ++rr) {
                    int r = rowbase + rf * 16 + (lane >> 2) + rr * 8;
                    float gs = sGS[r];
                    float2 x0 = *(const float2*)(x + (size_t)(row0 + r) * 512 + dc);
                    uint32_t off = (uint32_t)r * 1024 + (((uint32_t)(2 * dc)) ^ (((uint32_t)r & 7) << 4));
                    uint32_t xh = *(uint32_t*)(sm + O_XH + off);
                    uint32_t xm = *(uint32_t*)(sm + O_XM + off);
                    float xl0 = hlo(xh) + hlo(xm);
                    float xl1 = hhi(xh) + hhi(xm);
                    float o0 = x0.x * (d[rr * 2 + 0] + bv.x * gs) + xl0;
                    float o1 = x0.y * (d[rr * 2 + 1] + bv.y * gs) + xl1;
                    if (L == CROSS - 1) {
                        *(float2*)(out + (size_t)(row0 + r) * 512 + dc) = make_float2(o0, o1);
                    } else {
                        uint32_t hw, mw;
                        split2h(o0, o1, hw, mw);
                        *(uint32_t*)(sm + O_XH + off) = hw;
                        *(uint32_t*)(sm + O_XM + off) = mw;
                    }
                }
            }
        }
    }
}

extern "C" void kernel_launch(void* const* d_in, const int* in_sizes, int n_in,
                              void* d_out, int out_size) {
    const float* x    = (const float*)d_in[0];
    const float* Vs   = (const float*)d_in[1];
    const float* Cs   = (const float*)d_in[2];
    const float* Us   = (const float*)d_in[3];
    const float* bias = (const float*)d_in[4];
    const float* gate = (const float*)d_in[5];
    float* out = (float*)d_out;

    const int total = NPASS * 16384 + 4096;
    prep_kernel<<<(total + 255) / 256, 256>>>(Vs, Cs, Us, gate);

    int rows = in_sizes[0] / 512;
    int grid = rows / 64;

    cudaFuncSetAttribute(dcn_kernel, cudaFuncAttributeMaxDynamicSharedMemorySize, SMEM_BYTES);
    dcn_kernel<<<grid, THREADS, SMEM_BYTES>>>(x, bias, out);
}

// round 11
// speedup vs baseline: 8.2014x; 1.1581x over previous
#include <cuda_runtime.h>
#include <cuda_fp16.h>
#include <stdint.h>

#define CROSS   3
#define THREADS 512
#define NPASS   (CROSS * 17)

// ---------------- fragment-layout weight blob ----------------
// u32 index: (((g*8 + cg)*8 + (s*2+t))*32 + lane)*4 + q
// value: halves W_g[n][k], W_g[n][k+1] with
//   n = cg*32 + t*16 + (q&1)*8 + (lane>>2)
//   k = s*16 + (q>>1)*8 + 2*(lane&3)
__device__ __align__(16) uint32_t gWF[NPASS * 8192];
// gate plane image: [8 n][512 k] fp16, rowstride 1024B
__device__ __align__(16) __half gGB[4096];

__global__ void prep_kernel(const float* __restrict__ Vs,
                            const float* __restrict__ Cs,
                            const float* __restrict__ Us,
                            const float* __restrict__ gw) {
    int idx = blockIdx.x * 256 + threadIdx.x;
    const int NF = NPASS * 8192;
    if (idx < NF) {
        int u = idx;
        int q    = u & 3;  u >>= 2;
        int lane = u & 31; u >>= 5;
        int st   = u & 7;  u >>= 3;
        int cg   = u & 7;  u >>= 3;
        int g    = u;
        int s = st >> 1, t = st & 1;
        int n = cg * 32 + t * 16 + (q & 1) * 8 + (lane >> 2);
        int k = s * 16 + ((q >> 1) & 1) * 8 + 2 * (lane & 3);
        int L = g / 17, p = g - L * 17;
        float w0, w1;
        if (p < 8) {
            const float* src = Vs + (size_t)(L * 256 + n) * 512 + p * 64 + k;
            w0 = src[0]; w1 = src[1];
        } else if (p == 8) {
            const float* src = Cs + (size_t)L * 16384 + n * 64 + k;
            w0 = src[0]; w1 = src[1];
        } else {
            int qq = p - 9, h = qq >> 2, c = qq & 3;
            const float* src = Us + ((size_t)(L * 4 + c) * 512 + h * 256 + n) * 64 + k;
            w0 = src[0]; w1 = src[1];
        }
        __half h0 = __float2half_rn(w0), h1 = __float2half_rn(w1);
        gWF[idx] = (uint32_t)*(unsigned short*)&h0 | ((uint32_t)*(unsigned short*)&h1 << 16);
        return;
    }
    idx -= NF;
    if (idx < 4096) {
        int n = idx >> 9, k = idx & 511;
        float w = (n < 4) ? gw[k * 4 + n] : 0.f;
        gGB[(n * 1024 + ((2 * k) ^ ((n & 7) << 4))) >> 1] = __float2half_rn(w);
    }
}

// ---------------- warp-level primitives ----------------
__device__ __forceinline__ uint32_t s2u(const void* p) {
    uint32_t a;
    asm("{ .reg .u64 t; cvta.to.shared.u64 t, %1; cvt.u32.u64 %0, t; }" : "=r"(a) : "l"(p));
    return a;
}
__device__ __forceinline__ void ldsm4(uint32_t r[4], uint32_t addr) {
    asm volatile("ldmatrix.sync.aligned.m8n8.x4.shared.b16 {%0,%1,%2,%3}, [%4];"
                 : "=r"(r[0]), "=r"(r[1]), "=r"(r[2]), "=r"(r[3]) : "r"(addr));
}
__device__ __forceinline__ void ldsm2(uint32_t r[2], uint32_t addr) {
    asm volatile("ldmatrix.sync.aligned.m8n8.x2.shared.b16 {%0,%1}, [%2];"
                 : "=r"(r[0]), "=r"(r[1]) : "r"(addr));
}
__device__ __forceinline__ void mma_f16(float d[4], const uint32_t a[4], const uint32_t b0, const uint32_t b1) {
    asm volatile("mma.sync.aligned.m16n8k16.row.col.f32.f16.f16.f32 "
                 "{%0,%1,%2,%3}, {%4,%5,%6,%7}, {%8,%9}, {%0,%1,%2,%3};"
                 : "+f"(d[0]), "+f"(d[1]), "+f"(d[2]), "+f"(d[3])
                 : "r"(a[0]), "r"(a[1]), "r"(a[2]), "r"(a[3]), "r"(b0), "r"(b1));
}
__device__ __forceinline__ float fast_tanh(float x) {
    asm("tanh.approx.f32 %0, %0;" : "+f"(x));
    return x;
}
__device__ __forceinline__ uint32_t packh(float a, float b) {
    __half2 p = __floats2half2_rn(a, b);
    return *(uint32_t*)&p;
}
__device__ __forceinline__ void split2h(float a, float b, uint32_t& hw, uint32_t& mw) {
    __half h0 = __float2half_rn(a), h1 = __float2half_rn(b);
    __half m0 = __float2half_rn(a - __half2float(h0));
    __half m1 = __float2half_rn(b - __half2float(h1));
    hw = (uint32_t)*(unsigned short*)&h0 | ((uint32_t)*(unsigned short*)&h1 << 16);
    mw = (uint32_t)*(unsigned short*)&m0 | ((uint32_t)*(unsigned short*)&m1 << 16);
}
__device__ __forceinline__ float hlo(uint32_t w) {
    unsigned short s = (unsigned short)(w & 0xFFFF);
    return __half2float(*(__half*)&s);
}
__device__ __forceinline__ float hhi(uint32_t w) {
    unsigned short s = (unsigned short)(w >> 16);
    return __half2float(*(__half*)&s);
}
__device__ __forceinline__ void copy16(char* dst, const char* src, int bytes, int tid) {
    const float4* s = (const float4*)src;
    float4* d = (float4*)dst;
    for (int i = tid; i < bytes / 16; i += THREADS) d[i] = s[i];
}

// warp tile = 32 rows x 32 cols. acc[rowfrag 2][n16 2][n8 2][4].
// A via ldsm from smem plane; B via direct LDG.128 of fragment blob.
__device__ __forceinline__ void mma_ldg(
    uint32_t aB0, uint32_t aB1,
    const uint4* __restrict__ wp,        // gWF + g*2048 + cg*256 + lane
    const uint32_t kx[4],
    float (&acc)[2][2][2][4])
{
    uint4 b[8];
    #pragma unroll
    for (int i = 0; i < 8; ++i) b[i] = __ldg(wp + i * 32);
    #pragma unroll
    for (int s = 0; s < 4; ++s) {
        uint32_t a0[4], a1[4];
        ldsm4(a0, aB0 + kx[s]);
        ldsm4(a1, aB1 + kx[s]);
        const uint4 b0 = b[s * 2 + 0];
        const uint4 b1 = b[s * 2 + 1];
        mma_f16(acc[0][0][0], a0, b0.x, b0.z);
        mma_f16(acc[0][0][1], a0, b0.y, b0.w);
        mma_f16(acc[0][1][0], a0, b1.x, b1.z);
        mma_f16(acc[0][1][1], a0, b1.y, b1.w);
        mma_f16(acc[1][0][0], a1, b0.x, b0.z);
        mma_f16(acc[1][0][1], a1, b0.y, b0.w);
        mma_f16(acc[1][1][0], a1, b1.x, b1.z);
        mma_f16(acc[1][1][1], a1, b1.y, b1.w);
    }
}

#define ZEROACC                                       \
    _Pragma("unroll") for (int zi = 0; zi < 2; ++zi)  \
    _Pragma("unroll") for (int zj = 0; zj < 2; ++zj)  \
    _Pragma("unroll") for (int zk = 0; zk < 2; ++zk)  \
    _Pragma("unroll") for (int zl = 0; zl < 4; ++zl) acc[zi][zj][zk][zl] = 0.f;

// smem byte offsets
#define O_XH 0          // x_l hi plane  [64][512] fp16 (64KB)
#define O_XM 65536      // x_l mid plane (64KB)
#define O_V  131072     // v / c' plane  [64][256] fp16 (32KB)
#define O_GT 163840     // gate plane (8KB, staged once)
#define O_G  172032     // sG [64][4] f32
#define O_GS 173056     // sGS [64] f32
#define SMEM_BYTES 173312

__global__ void __launch_bounds__(THREADS, 1)
dcn_kernel(const float* __restrict__ x,
           const float* __restrict__ bias,
           float* __restrict__ out)
{
    extern __shared__ char sm[];
    const uint32_t sb = s2u(sm);
    const int tid = threadIdx.x;
    const int w = tid >> 5, lane = tid & 31;
    const int row0 = blockIdx.x * 64;
    const int rowbase = (w & 1) * 32;
    const int cg = w >> 1;                 // 0..7 (32-col groups)
    const int nbase = cg * 32;
    const int ec = cg >> 1;                // expert for C phase

    // ---- hoisted ldsm addressing (per-thread constants; A-side only) ----
    const uint32_t lr = (uint32_t)(lane & 15);
    const uint32_t lk = (uint32_t)((lane >> 4) << 4);
    const uint32_t csw = (uint32_t)((lane & 7) << 4);
    uint32_t kx[4];
    #pragma unroll
    for (int s = 0; s < 4; ++s) kx[s] = ((uint32_t)(s * 32) + lk) ^ csw;
    const uint32_t aX0 = sb + O_XH + ((uint32_t)rowbase + 0  + lr) * 1024;
    const uint32_t aX1 = sb + O_XH + ((uint32_t)rowbase + 16 + lr) * 1024;
    const uint32_t aV0 = sb + O_V  + ((uint32_t)rowbase + 0  + lr) * 512;
    const uint32_t aV1 = sb + O_V  + ((uint32_t)rowbase + 16 + lr) * 512;

    // per-thread fragment pointer base: + g*2048 per pass
    const uint4* __restrict__ wf0 = (const uint4*)gWF + (uint32_t)(cg * 256 + lane);

    float* sG  = (float*)(sm + O_G);
    float* sGS = (float*)(sm + O_GS);

    // ---- init: x -> fp16 hi/mid planes; gate plane staged once ----
    copy16(sm + O_GT, (const char*)gGB, 8192, tid);
    for (int i = tid; i < 64 * 256; i += THREADS) {
        int r = i >> 8, kp = i & 255;
        float2 v = *(const float2*)(x + (size_t)(row0 + r) * 512 + 2 * kp);
        uint32_t hw, mw;
        split2h(v.x, v.y, hw, mw);
        uint32_t off = (uint32_t)r * 1024 + (((uint32_t)(4 * kp)) ^ (((uint32_t)r & 7) << 4));
        *(uint32_t*)(sm + O_XH + off) = hw;
        *(uint32_t*)(sm + O_XM + off) = mw;
    }
    __syncthreads();

    float acc[2][2][2][4];

    #pragma unroll 1
    for (int L = 0; L < CROSS; ++L) {
        const int g0 = L * 17;
        const uint4* __restrict__ wL = wf0 + (uint32_t)g0 * 2048;

        // ---- gate (warps 0-3): reads XH + static gate plane ----
        if (w < 4) {
            float ga[4] = {0.f, 0.f, 0.f, 0.f};
            #pragma unroll 4
            for (int s = 0; s < 32; ++s) {
                uint32_t kb = s * 32;
                uint32_t r = (uint32_t)(w * 16) + lr;
                uint32_t ah[4];
                ldsm4(ah, sb + O_XH + r * 1024 + ((kb + lk) ^ ((r & 7) << 4)));
                uint32_t bn = lane & 7;
                uint32_t bk = kb + (((lane >> 3) & 1) << 4);
                uint32_t bh[2];
                ldsm2(bh, sb + O_GT + bn * 1024 + (bk ^ ((bn & 7) << 4)));
                mma_f16(ga, ah, bh[0], bh[1]);
            }
            int c0 = (lane & 3) * 2;
            if (c0 < 4) {
                int r1 = w * 16 + (lane >> 2);
                sG[r1 * 4 + c0] = ga[0];       sG[r1 * 4 + c0 + 1] = ga[1];
                sG[(r1 + 8) * 4 + c0] = ga[2]; sG[(r1 + 8) * 4 + c0 + 1] = ga[3];
            }
        }

        // ---- V: v = tanh(Vs @ x_l), K=512, 8 barrier-free passes ----
        ZEROACC;
        #pragma unroll
        for (int c = 0; c < 8; ++c)
            mma_ldg(aX0 + c * 128, aX1 + c * 128, wL + c * 2048, kx, acc);
        // V epilogue -> V plane
        #pragma unroll
        for (int rf = 0; rf < 2; ++rf)
        #pragma unroll
        for (int t = 0; t < 2; ++t)
        #pragma unroll
        for (int nb = 0; nb < 2; ++nb) {
            float* d = acc[rf][t][nb];
            int n = nbase + t * 16 + nb * 8 + (lane & 3) * 2;
            #pragma unroll
            for (int rr = 0; rr < 2; ++rr) {
                int r = rowbase + rf * 16 + (lane >> 2) + rr * 8;
                uint32_t off = (uint32_t)r * 512 + (((uint32_t)(2 * n)) ^ (((uint32_t)r & 7) << 4));
                *(uint32_t*)(sm + O_V + off) =
                    packh(fast_tanh(d[rr * 2 + 0]), fast_tanh(d[rr * 2 + 1]));
            }
        }
        __syncthreads();   // V plane + sG visible to all

        if (tid < 64)
            sGS[tid] = sG[tid * 4] + sG[tid * 4 + 1] + sG[tid * 4 + 2] + sG[tid * 4 + 3];

        // ---- C: block diagonal, one pass ----
        ZEROACC;
        mma_ldg(aV0 + ec * 128, aV1 + ec * 128, wL + 8 * 2048, kx, acc);
        __syncthreads();   // all C-mma reads of V done before overwrite
        #pragma unroll
        for (int rf = 0; rf < 2; ++rf)
        #pragma unroll
        for (int t = 0; t < 2; ++t)
        #pragma unroll
        for (int nb = 0; nb < 2; ++nb) {
            float* d = acc[rf][t][nb];
            int n = nbase + t * 16 + nb * 8 + (lane & 3) * 2;
            #pragma unroll
            for (int rr = 0; rr < 2; ++rr) {
                int r = rowbase + rf * 16 + (lane >> 2) + rr * 8;
                float g = sG[r * 4 + ec];
                uint32_t off = (uint32_t)r * 512 + (((uint32_t)(2 * n)) ^ (((uint32_t)r & 7) << 4));
                *(uint32_t*)(sm + O_V + off) =
                    packh(g * fast_tanh(d[rr * 2 + 0]), g * fast_tanh(d[rr * 2 + 1]));
            }
        }
        __syncthreads();   // c' visible

        // ---- U: two 256-d halves x 4 expert chunks; fused combine ----
        #pragma unroll 1
        for (int h = 0; h < 2; ++h) {
            ZEROACC;
            #pragma unroll
            for (int c = 0; c < 4; ++c)
                mma_ldg(aV0 + c * 128, aV1 + c * 128,
                        wL + (9 + h * 4 + c) * 2048, kx, acc);
            // epilogue: out = x0*(u + bias*gs) + x_l
            #pragma unroll
            for (int rf = 0; rf < 2; ++rf)
            #pragma unroll
            for (int t = 0; t < 2; ++t)
            #pragma unroll
            for (int nb = 0; nb < 2; ++nb) {
                float* d = acc[rf][t][nb];
                int dc = h * 256 + nbase + t * 16 + nb * 8 + (lane & 3) * 2;
                float2 bv = *(const float2*)(bias + L * 512 + dc);
                #pragma unroll
                for (int rr = 0; rr < 2; ++rr) {
                    int r = rowbase + rf * 16 + (lane >> 2) + rr * 8;
                    float gs = sGS[r];
                    float2 x0 = *(const float2*)(x + (size_t)(row0 + r) * 512 + dc);
                    uint32_t off = (uint32_t)r * 1024 + (((uint32_t)(2 * dc)) ^ (((uint32_t)r & 7) << 4));
                    uint32_t xh = *(uint32_t*)(sm + O_XH + off);
                    uint32_t xm = *(uint32_t*)(sm + O_XM + off);
                    float xl0 = hlo(xh) + hlo(xm);
                    float xl1 = hhi(xh) + hhi(xm);
                    float o0 = x0.x * (d[rr * 2 + 0] + bv.x * gs) + xl0;
                    float o1 = x0.y * (d[rr * 2 + 1] + bv.y * gs) + xl1;
                    if (L == CROSS - 1) {
                        *(float2*)(out + (size_t)(row0 + r) * 512 + dc) = make_float2(o0, o1);
                    } else {
                        uint32_t hw, mw;
                        split2h(o0, o1, hw, mw);
                        *(uint32_t*)(sm + O_XH + off) = hw;
                        *(uint32_t*)(sm + O_XM + off) = mw;
                    }
                }
            }
        }
        __syncthreads();   // XH/XM updated before next layer's reads
    }
}

extern "C" void kernel_launch(void* const* d_in, const int* in_sizes, int n_in,
                              void* d_out, int out_size) {
    const float* x    = (const float*)d_in[0];
    const float* Vs   = (const float*)d_in[1];
    const float* Cs   = (const float*)d_in[2];
    const float* Us   = (const float*)d_in[3];
    const float* bias = (const float*)d_in[4];
    const float* gate = (const float*)d_in[5];
    float* out = (float*)d_out;

    const int total = NPASS * 8192 + 4096;
    prep_kernel<<<(total + 255) / 256, 256>>>(Vs, Cs, Us, gate);

    int rows = in_sizes[0] / 512;
    int grid = rows / 64;

    cudaFuncSetAttribute(dcn_kernel, cudaFuncAttributeMaxDynamicSharedMemorySize, SMEM_BYTES);
    dcn_kernel<<<grid, THREADS, SMEM_BYTES>>>(x, bias, out);
}

// round 12
// speedup vs baseline: 9.7131x; 1.1843x over previous
#include <cuda_runtime.h>
#include <cuda_fp16.h>
#include <stdint.h>

#define CROSS   3
#define THREADS 256
#define NPASS   (CROSS * 17)

// ---------------- fragment-layout weight blob ----------------
// u32 index: (((g*8 + cg)*8 + (s*2+t))*32 + lane)*4 + q
// value: halves W_g[n][k], W_g[n][k+1] with
//   n = cg*32 + t*16 + (q&1)*8 + (lane>>2)
//   k = s*16 + (q>>1)*8 + 2*(lane&3)
__device__ __align__(16) uint32_t gWF[NPASS * 8192];
// gate plane image: [8 n][512 k] fp16, rowstride 1024B
__device__ __align__(16) __half gGB[4096];

__global__ void prep_kernel(const float* __restrict__ Vs,
                            const float* __restrict__ Cs,
                            const float* __restrict__ Us,
                            const float* __restrict__ gw) {
    int idx = blockIdx.x * 256 + threadIdx.x;
    const int NF = NPASS * 8192;
    if (idx < NF) {
        int u = idx;
        int q    = u & 3;  u >>= 2;
        int lane = u & 31; u >>= 5;
        int st   = u & 7;  u >>= 3;
        int cg   = u & 7;  u >>= 3;
        int g    = u;
        int s = st >> 1, t = st & 1;
        int n = cg * 32 + t * 16 + (q & 1) * 8 + (lane >> 2);
        int k = s * 16 + ((q >> 1) & 1) * 8 + 2 * (lane & 3);
        int L = g / 17, p = g - L * 17;
        float w0, w1;
        if (p < 8) {
            const float* src = Vs + (size_t)(L * 256 + n) * 512 + p * 64 + k;
            w0 = src[0]; w1 = src[1];
        } else if (p == 8) {
            const float* src = Cs + (size_t)L * 16384 + n * 64 + k;
            w0 = src[0]; w1 = src[1];
        } else {
            int qq = p - 9, h = qq >> 2, c = qq & 3;
            const float* src = Us + ((size_t)(L * 4 + c) * 512 + h * 256 + n) * 64 + k;
            w0 = src[0]; w1 = src[1];
        }
        __half h0 = __float2half_rn(w0), h1 = __float2half_rn(w1);
        gWF[idx] = (uint32_t)*(unsigned short*)&h0 | ((uint32_t)*(unsigned short*)&h1 << 16);
        return;
    }
    idx -= NF;
    if (idx < 4096) {
        int n = idx >> 9, k = idx & 511;
        float w = (n < 4) ? gw[k * 4 + n] : 0.f;
        gGB[(n * 1024 + ((2 * k) ^ ((n & 7) << 4))) >> 1] = __float2half_rn(w);
    }
}

// ---------------- warp-level primitives ----------------
__device__ __forceinline__ uint32_t s2u(const void* p) {
    uint32_t a;
    asm("{ .reg .u64 t; cvta.to.shared.u64 t, %1; cvt.u32.u64 %0, t; }" : "=r"(a) : "l"(p));
    return a;
}
__device__ __forceinline__ void ldsm4(uint32_t r[4], uint32_t addr) {
    asm volatile("ldmatrix.sync.aligned.m8n8.x4.shared.b16 {%0,%1,%2,%3}, [%4];"
                 : "=r"(r[0]), "=r"(r[1]), "=r"(r[2]), "=r"(r[3]) : "r"(addr));
}
__device__ __forceinline__ void ldsm2(uint32_t r[2], uint32_t addr) {
    asm volatile("ldmatrix.sync.aligned.m8n8.x2.shared.b16 {%0,%1}, [%2];"
                 : "=r"(r[0]), "=r"(r[1]) : "r"(addr));
}
__device__ __forceinline__ void mma_f16(float d[4], const uint32_t a[4], const uint32_t b0, const uint32_t b1) {
    asm volatile("mma.sync.aligned.m16n8k16.row.col.f32.f16.f16.f32 "
                 "{%0,%1,%2,%3}, {%4,%5,%6,%7}, {%8,%9}, {%0,%1,%2,%3};"
                 : "+f"(d[0]), "+f"(d[1]), "+f"(d[2]), "+f"(d[3])
                 : "r"(a[0]), "r"(a[1]), "r"(a[2]), "r"(a[3]), "r"(b0), "r"(b1));
}
__device__ __forceinline__ float fast_tanh(float x) {
    asm("tanh.approx.f32 %0, %0;" : "+f"(x));
    return x;
}
__device__ __forceinline__ uint32_t packh(float a, float b) {
    __half2 p = __floats2half2_rn(a, b);
    return *(uint32_t*)&p;
}
__device__ __forceinline__ void split2h(float a, float b, uint32_t& hw, uint32_t& mw) {
    __half h0 = __float2half_rn(a), h1 = __float2half_rn(b);
    __half m0 = __float2half_rn(a - __half2float(h0));
    __half m1 = __float2half_rn(b - __half2float(h1));
    hw = (uint32_t)*(unsigned short*)&h0 | ((uint32_t)*(unsigned short*)&h1 << 16);
    mw = (uint32_t)*(unsigned short*)&m0 | ((uint32_t)*(unsigned short*)&m1 << 16);
}
__device__ __forceinline__ float hlo(uint32_t w) {
    unsigned short s = (unsigned short)(w & 0xFFFF);
    return __half2float(*(__half*)&s);
}
__device__ __forceinline__ float hhi(uint32_t w) {
    unsigned short s = (unsigned short)(w >> 16);
    return __half2float(*(__half*)&s);
}
__device__ __forceinline__ void copy16(char* dst, const char* src, int bytes, int tid) {
    const float4* s = (const float4*)src;
    float4* d = (float4*)dst;
    for (int i = tid; i < bytes / 16; i += THREADS) d[i] = s[i];
}

// warp tile = 32 rows x 32 cols. acc[rowfrag 2][n16 2][n8 2][4].
// A via ldsm from smem plane; B via direct LDG.128 of fragment blob.
__device__ __forceinline__ void mma_ldg(
    uint32_t aB0, uint32_t aB1,
    const uint4* __restrict__ wp,        // gWF + g*2048 + cg*256 + lane
    const uint32_t kx[4],
    float (&acc)[2][2][2][4])
{
    uint4 b[8];
    #pragma unroll
    for (int i = 0; i < 8; ++i) b[i] = __ldg(wp + i * 32);
    #pragma unroll
    for (int s = 0; s < 4; ++s) {
        uint32_t a0[4], a1[4];
        ldsm4(a0, aB0 + kx[s]);
        ldsm4(a1, aB1 + kx[s]);
        const uint4 b0 = b[s * 2 + 0];
        const uint4 b1 = b[s * 2 + 1];
        mma_f16(acc[0][0][0], a0, b0.x, b0.z);
        mma_f16(acc[0][0][1], a0, b0.y, b0.w);
        mma_f16(acc[0][1][0], a0, b1.x, b1.z);
        mma_f16(acc[0][1][1], a0, b1.y, b1.w);
        mma_f16(acc[1][0][0], a1, b0.x, b0.z);
        mma_f16(acc[1][0][1], a1, b0.y, b0.w);
        mma_f16(acc[1][1][0], a1, b1.x, b1.z);
        mma_f16(acc[1][1][1], a1, b1.y, b1.w);
    }
}

#define ZEROACC                                       \
    _Pragma("unroll") for (int zi = 0; zi < 2; ++zi)  \
    _Pragma("unroll") for (int zj = 0; zj < 2; ++zj)  \
    _Pragma("unroll") for (int zk = 0; zk < 2; ++zk)  \
    _Pragma("unroll") for (int zl = 0; zl < 4; ++zl) acc[zi][zj][zk][zl] = 0.f;

// smem byte offsets (32-row CTA)
#define O_XH 0          // x_l hi plane  [32][512] fp16 (32KB)
#define O_XM 32768      // x_l mid plane (32KB)
#define O_V  65536      // v / c' plane  [32][256] fp16 (16KB)
#define O_GT 81920      // gate plane (8KB, staged once)
#define O_G  90112      // sG [32][4] f32
#define O_GS 90624      // sGS [32] f32
#define SMEM_BYTES 90752

__global__ void __launch_bounds__(THREADS, 2)
dcn_kernel(const float* __restrict__ x,
           const float* __restrict__ bias,
           float* __restrict__ out)
{
    extern __shared__ char sm[];
    const uint32_t sb = s2u(sm);
    const int tid = threadIdx.x;
    const int w = tid >> 5, lane = tid & 31;
    const int row0 = blockIdx.x * 32;
    const int cg = w;                      // 0..7 (32-col groups)
    const int nbase = cg * 32;
    const int ec = cg >> 1;                // expert for C phase

    // ---- hoisted ldsm addressing (per-thread constants; A-side only) ----
    const uint32_t lr = (uint32_t)(lane & 15);
    const uint32_t lk = (uint32_t)((lane >> 4) << 4);
    const uint32_t csw = (uint32_t)((lane & 7) << 4);
    uint32_t kx[4];
    #pragma unroll
    for (int s = 0; s < 4; ++s) kx[s] = ((uint32_t)(s * 32) + lk) ^ csw;
    const uint32_t aX0 = sb + O_XH + (0  + lr) * 1024;
    const uint32_t aX1 = sb + O_XH + (16 + lr) * 1024;
    const uint32_t aV0 = sb + O_V  + (0  + lr) * 512;
    const uint32_t aV1 = sb + O_V  + (16 + lr) * 512;

    // per-thread fragment pointer base: + g*2048 per pass
    const uint4* __restrict__ wf0 = (const uint4*)gWF + (uint32_t)(cg * 256 + lane);

    float* sG  = (float*)(sm + O_G);
    float* sGS = (float*)(sm + O_GS);

    // ---- init: x -> fp16 hi/mid planes; gate plane staged once ----
    copy16(sm + O_GT, (const char*)gGB, 8192, tid);
    for (int i = tid; i < 32 * 256; i += THREADS) {
        int r = i >> 8, kp = i & 255;
        float2 v = *(const float2*)(x + (size_t)(row0 + r) * 512 + 2 * kp);
        uint32_t hw, mw;
        split2h(v.x, v.y, hw, mw);
        uint32_t off = (uint32_t)r * 1024 + (((uint32_t)(4 * kp)) ^ (((uint32_t)r & 7) << 4));
        *(uint32_t*)(sm + O_XH + off) = hw;
        *(uint32_t*)(sm + O_XM + off) = mw;
    }
    __syncthreads();

    float acc[2][2][2][4];

    #pragma unroll 1
    for (int L = 0; L < CROSS; ++L) {
        const int g0 = L * 17;
        const uint4* __restrict__ wL = wf0 + (uint32_t)g0 * 2048;

        // ---- gate (warps 0-1): reads XH + static gate plane ----
        if (w < 2) {
            float ga[4] = {0.f, 0.f, 0.f, 0.f};
            #pragma unroll 4
            for (int s = 0; s < 32; ++s) {
                uint32_t kb = s * 32;
                uint32_t r = (uint32_t)(w * 16) + lr;
                uint32_t ah[4];
                ldsm4(ah, sb + O_XH + r * 1024 + ((kb + lk) ^ ((r & 7) << 4)));
                uint32_t bn = lane & 7;
                uint32_t bk = kb + (((lane >> 3) & 1) << 4);
                uint32_t bh[2];
                ldsm2(bh, sb + O_GT + bn * 1024 + (bk ^ ((bn & 7) << 4)));
                mma_f16(ga, ah, bh[0], bh[1]);
            }
            int c0 = (lane & 3) * 2;
            if (c0 < 4) {
                int r1 = w * 16 + (lane >> 2);
                sG[r1 * 4 + c0] = ga[0];       sG[r1 * 4 + c0 + 1] = ga[1];
                sG[(r1 + 8) * 4 + c0] = ga[2]; sG[(r1 + 8) * 4 + c0 + 1] = ga[3];
            }
        }

        // ---- V: v = tanh(Vs @ x_l), K=512, 8 barrier-free passes ----
        ZEROACC;
        #pragma unroll
        for (int c = 0; c < 8; ++c)
            mma_ldg(aX0 + c * 128, aX1 + c * 128, wL + c * 2048, kx, acc);
        // V epilogue -> V plane
        #pragma unroll
        for (int rf = 0; rf < 2; ++rf)
        #pragma unroll
        for (int t = 0; t < 2; ++t)
        #pragma unroll
        for (int nb = 0; nb < 2; ++nb) {
            float* d = acc[rf][t][nb];
            int n = nbase + t * 16 + nb * 8 + (lane & 3) * 2;
            #pragma unroll
            for (int rr = 0; rr < 2; ++rr) {
                int r = rf * 16 + (lane >> 2) + rr * 8;
                uint32_t off = (uint32_t)r * 512 + (((uint32_t)(2 * n)) ^ (((uint32_t)r & 7) << 4));
                *(uint32_t*)(sm + O_V + off) =
                    packh(fast_tanh(d[rr * 2 + 0]), fast_tanh(d[rr * 2 + 1]));
            }
        }
        __syncthreads();   // V plane + sG visible to all

        if (tid < 32)
            sGS[tid] = sG[tid * 4] + sG[tid * 4 + 1] + sG[tid * 4 + 2] + sG[tid * 4 + 3];

        // ---- C: block diagonal, one pass ----
        ZEROACC;
        mma_ldg(aV0 + ec * 128, aV1 + ec * 128, wL + 8 * 2048, kx, acc);
        __syncthreads();   // all C-mma reads of V done before overwrite
        #pragma unroll
        for (int rf = 0; rf < 2; ++rf)
        #pragma unroll
        for (int t = 0; t < 2; ++t)
        #pragma unroll
        for (int nb = 0; nb < 2; ++nb) {
            float* d = acc[rf][t][nb];
            int n = nbase + t * 16 + nb * 8 + (lane & 3) * 2;
            #pragma unroll
            for (int rr = 0; rr < 2; ++rr) {
                int r = rf * 16 + (lane >> 2) + rr * 8;
                float g = sG[r * 4 + ec];
                uint32_t off = (uint32_t)r * 512 + (((uint32_t)(2 * n)) ^ (((uint32_t)r & 7) << 4));
                *(uint32_t*)(sm + O_V + off) =
                    packh(g * fast_tanh(d[rr * 2 + 0]), g * fast_tanh(d[rr * 2 + 1]));
            }
        }
        __syncthreads();   // c' visible

        // ---- U: two 256-d halves x 4 expert chunks; fused combine ----
        #pragma unroll 1
        for (int h = 0; h < 2; ++h) {
            ZEROACC;
            #pragma unroll
            for (int c = 0; c < 4; ++c)
                mma_ldg(aV0 + c * 128, aV1 + c * 128,
                        wL + (9 + h * 4 + c) * 2048, kx, acc);
            // epilogue: out = x0*(u + bias*gs) + x_l
            #pragma unroll
            for (int rf = 0; rf < 2; ++rf)
            #pragma unroll
            for (int t = 0; t < 2; ++t)
            #pragma unroll
            for (int nb = 0; nb < 2; ++nb) {
                float* d = acc[rf][t][nb];
                int dc = h * 256 + nbase + t * 16 + nb * 8 + (lane & 3) * 2;
                float2 bv = *(const float2*)(bias + L * 512 + dc);
                #pragma unroll
                for (int rr = 0; rr < 2; ++rr) {
                    int r = rf * 16 + (lane >> 2) + rr * 8;
                    float gs = sGS[r];
                    float2 x0 = *(const float2*)(x + (size_t)(row0 + r) * 512 + dc);
                    uint32_t off = (uint32_t)r * 1024 + (((uint32_t)(2 * dc)) ^ (((uint32_t)r & 7) << 4));
                    uint32_t xh = *(uint32_t*)(sm + O_XH + off);
                    uint32_t xm = *(uint32_t*)(sm + O_XM + off);
                    float xl0 = hlo(xh) + hlo(xm);
                    float xl1 = hhi(xh) + hhi(xm);
                    float o0 = x0.x * (d[rr * 2 + 0] + bv.x * gs) + xl0;
                    float o1 = x0.y * (d[rr * 2 + 1] + bv.y * gs) + xl1;
                    if (L == CROSS - 1) {
                        *(float2*)(out + (size_t)(row0 + r) * 512 + dc) = make_float2(o0, o1);
                    } else {
                        uint32_t hw, mw;
                        split2h(o0, o1, hw, mw);
                        *(uint32_t*)(sm + O_XH + off) = hw;
                        *(uint32_t*)(sm + O_XM + off) = mw;
                    }
                }
            }
        }
        __syncthreads();   // XH/XM updated before next layer's reads
    }
}

extern "C" void kernel_launch(void* const* d_in, const int* in_sizes, int n_in,
                              void* d_out, int out_size) {
    const float* x    = (const float*)d_in[0];
    const float* Vs   = (const float*)d_in[1];
    const float* Cs   = (const float*)d_in[2];
    const float* Us   = (const float*)d_in[3];
    const float* bias = (const float*)d_in[4];
    const float* gate = (const float*)d_in[5];
    float* out = (float*)d_out;

    const int total = NPASS * 8192 + 4096;
    prep_kernel<<<(total + 255) / 256, 256>>>(Vs, Cs, Us, gate);

    int rows = in_sizes[0] / 512;
    int grid = rows / 32;

    cudaFuncSetAttribute(dcn_kernel, cudaFuncAttributeMaxDynamicSharedMemorySize, SMEM_BYTES);
    dcn_kernel<<<grid, THREADS, SMEM_BYTES>>>(x, bias, out);
}